// round 4
// baseline (speedup 1.0000x reference)
#include <cuda_runtime.h>
#include <cuda_bf16.h>
#include <cuda_fp8.h>
#include <cstdint>

#define NTOK 8192
#define DIM 4096
#define ODIM 4096
#define NEXP 8
#define RNK 16
#define KLORA 128
#define SCALING_F 2.0f
#define MAXTHR 0.125f

// scales: corrections = ah*(bl*2^14) + (al*2^8)*(bh*2^6), both scaled 2^14
#define S_AL 256.0f
#define S_BH 64.0f
#define S_BL 16384.0f
#define INV_S 6.103515625e-05f   // 2^-14

// ---------------- device scratch --------------------------------------------
__device__ float g_w[NTOK * NEXP];
__device__ __nv_bfloat16 g_xhi[(size_t)NTOK * DIM];
__device__ uint8_t g_xa8h[(size_t)NTOK * DIM];
__device__ uint8_t g_xa8l[(size_t)NTOK * DIM];
__device__ __nv_bfloat16 g_Whi[(size_t)ODIM * DIM];
__device__ uint8_t g_Wb8h[(size_t)ODIM * DIM];
__device__ uint8_t g_Wb8l[(size_t)ODIM * DIM];
__device__ __nv_bfloat16 g_Ahi[KLORA * DIM];
__device__ uint8_t g_Ab8h[KLORA * DIM];
__device__ uint8_t g_Ab8l[KLORA * DIM];
__device__ __nv_bfloat16 g_Bchi[ODIM * KLORA];
__device__ uint8_t g_Bc8h[ODIM * KLORA];
__device__ uint8_t g_Bc8l[ODIM * KLORA];
__device__ __nv_bfloat16 g_ghi[NTOK * KLORA];
__device__ uint8_t g_g8h[NTOK * KLORA];
__device__ uint8_t g_g8l[NTOK * KLORA];

// ---------------- PTX helpers -----------------------------------------------
__device__ __forceinline__ uint32_t smem_u32(const void* p) {
    uint32_t a;
    asm("{ .reg .u64 t; cvta.to.shared.u64 t, %1; cvt.u32.u64 %0, t; }" : "=r"(a) : "l"(p));
    return a;
}
__device__ __forceinline__ void cp16(uint32_t dst, const void* src) {
    asm volatile("cp.async.cg.shared.global [%0], [%1], 16;" :: "r"(dst), "l"(src));
}
#define CP_COMMIT() asm volatile("cp.async.commit_group;" ::: "memory")
#define CP_WAIT1()  asm volatile("cp.async.wait_group 1;" ::: "memory")

__device__ __forceinline__ void ldsm4(uint32_t& r0, uint32_t& r1, uint32_t& r2, uint32_t& r3,
                                      uint32_t addr) {
    asm volatile("ldmatrix.sync.aligned.m8n8.x4.shared.b16 {%0,%1,%2,%3}, [%4];"
                 : "=r"(r0), "=r"(r1), "=r"(r2), "=r"(r3) : "r"(addr));
}
__device__ __forceinline__ void mma16816(float* d, const uint32_t* a, const uint32_t* b) {
    asm volatile("mma.sync.aligned.m16n8k16.row.col.f32.bf16.bf16.f32 "
                 "{%0,%1,%2,%3}, {%4,%5,%6,%7}, {%8,%9}, {%0,%1,%2,%3};"
                 : "+f"(d[0]), "+f"(d[1]), "+f"(d[2]), "+f"(d[3])
                 : "r"(a[0]), "r"(a[1]), "r"(a[2]), "r"(a[3]), "r"(b[0]), "r"(b[1]));
}
__device__ __forceinline__ void mma8(float* d, const uint32_t* a, const uint32_t* b) {
    asm volatile("mma.sync.aligned.m16n8k32.row.col.f32.e4m3.e4m3.f32 "
                 "{%0,%1,%2,%3}, {%4,%5,%6,%7}, {%8,%9}, {%0,%1,%2,%3};"
                 : "+f"(d[0]), "+f"(d[1]), "+f"(d[2]), "+f"(d[3])
                 : "r"(a[0]), "r"(a[1]), "r"(a[2]), "r"(a[3]), "r"(b[0]), "r"(b[1]));
}

// ---------------- conversion helpers ----------------------------------------
__device__ __forceinline__ uint8_t to_e4m3(float v) {
    return (uint8_t)__nv_cvt_float_to_fp8(v, __NV_SATFINITE, __NV_E4M3);
}
// which: 0 = x (A-operand), 1 = W (B-op), 2 = A_w (B-op)
__global__ void split_kernel(const float* __restrict__ src, int which, int n4) {
    __nv_bfloat16* hi; uint8_t *q1, *q2; int bop;
    if (which == 0)      { hi = g_xhi; q1 = g_xa8h; q2 = g_xa8l; bop = 0; }
    else if (which == 1) { hi = g_Whi; q1 = g_Wb8h; q2 = g_Wb8l; bop = 1; }
    else                 { hi = g_Ahi; q1 = g_Ab8h; q2 = g_Ab8l; bop = 1; }
    int i = blockIdx.x * blockDim.x + threadIdx.x;
    if (i >= n4) return;
    float4 v = ((const float4*)src)[i];
    float vv[4] = {v.x, v.y, v.z, v.w};
    __nv_bfloat16 h[4]; float l[4];
    uchar4 c1, c2;
    uint8_t* p1 = &c1.x; uint8_t* p2 = &c2.x;
#pragma unroll
    for (int j = 0; j < 4; j++) {
        h[j] = __float2bfloat16(vv[j]);
        float hf = __bfloat162float(h[j]);
        l[j] = vv[j] - hf;
        if (bop) { p1[j] = to_e4m3(hf * S_BH); p2[j] = to_e4m3(l[j] * S_BL); }
        else     { p1[j] = to_e4m3(hf);        p2[j] = to_e4m3(l[j] * S_AL); }
    }
    ((__nv_bfloat162*)hi)[2 * i]     = __nv_bfloat162(h[0], h[1]);
    ((__nv_bfloat162*)hi)[2 * i + 1] = __nv_bfloat162(h[2], h[3]);
    ((uchar4*)q1)[i] = c1;
    ((uchar4*)q2)[i] = c2;
}
__global__ void build_bc_kernel(const float* __restrict__ Bw) {
    int idx = blockIdx.x * blockDim.x + threadIdx.x;   // o*128 + k
    if (idx >= ODIM * KLORA) return;
    int o = idx >> 7, k = idx & 127;
    int e = k >> 4, r = k & 15;
    float v = Bw[((size_t)e * ODIM + o) * RNK + r];
    __nv_bfloat16 h = __float2bfloat16(v);
    float hf = __bfloat162float(h);
    g_Bchi[idx] = h;
    g_Bc8h[idx] = to_e4m3(hf * S_BH);
    g_Bc8l[idx] = to_e4m3((v - hf) * S_BL);
}

// ---------------- gate kernel -----------------------------------------------
#define GT 4
__global__ void gate_kernel(const float* __restrict__ x,
                            const float* __restrict__ Wg,
                            const float* __restrict__ Wt,
                            const float* __restrict__ bt) {
    int n0 = blockIdx.x * GT;
    int tid = threadIdx.x;
    float acc[GT][9];
#pragma unroll
    for (int t = 0; t < GT; t++)
#pragma unroll
        for (int i = 0; i < 9; i++) acc[t][i] = 0.f;
    for (int d = tid; d < DIM; d += 256) {
        float wv[9];
#pragma unroll
        for (int e = 0; e < NEXP; e++) wv[e] = Wg[e * DIM + d];
        wv[8] = Wt[d];
#pragma unroll
        for (int t = 0; t < GT; t++) {
            float xv = x[(size_t)(n0 + t) * DIM + d];
#pragma unroll
            for (int i = 0; i < 9; i++) acc[t][i] = fmaf(xv, wv[i], acc[t][i]);
        }
    }
#pragma unroll
    for (int t = 0; t < GT; t++)
#pragma unroll
        for (int i = 0; i < 9; i++)
#pragma unroll
            for (int off = 16; off; off >>= 1)
                acc[t][i] += __shfl_down_sync(0xffffffffu, acc[t][i], off);
    __shared__ float sred[8][GT][9];
    int warp = tid >> 5, lane = tid & 31;
    if (lane == 0)
#pragma unroll
        for (int t = 0; t < GT; t++)
#pragma unroll
            for (int i = 0; i < 9; i++) sred[warp][t][i] = acc[t][i];
    __syncthreads();
    if (tid < GT) {
        int t = tid;
        float v[9];
#pragma unroll
        for (int i = 0; i < 9; i++) {
            float s = 0.f;
#pragma unroll
            for (int w2 = 0; w2 < 8; w2++) s += sred[w2][t][i];
            v[i] = s;
        }
        float mx = v[0];
#pragma unroll
        for (int e = 1; e < NEXP; e++) mx = fmaxf(mx, v[e]);
        float se = 0.f, gate[NEXP];
#pragma unroll
        for (int e = 0; e < NEXP; e++) { gate[e] = expf(v[e] - mx); se += gate[e]; }
        float inv = 1.f / se;
        float thr = MAXTHR / (1.f + expf(-(v[8] + bt[0])));
        float w[NEXP]; float ws = 0.f;
#pragma unroll
        for (int e = 0; e < NEXP; e++) {
            float a = gate[e] * inv - thr;
            w[e] = (a >= 0.f) ? a : 0.f;
            ws += w[e];
        }
        if (ws == 0.f) ws = 1.f;
        float sc = SCALING_F / ws;
#pragma unroll
        for (int e = 0; e < NEXP; e++) g_w[(n0 + t) * NEXP + e] = w[e] * sc;
    }
}

// ---------------- GEMM smem layout -------------------------------------------
#define RS 80              // bf16 tile row stride (conflict-free ldmatrix)
#define RS8 48             // fp8 tile row stride (conflict-free)
#define ABF_B (128 * RS)   // 10240
#define A8_B (128 * RS8)   // 6144
#define OFF_ABF 0
#define OFF_BBF ABF_B
#define OFF_A8H (2 * ABF_B)
#define OFF_A8L (2 * ABF_B + A8_B)
#define OFF_B8L (2 * ABF_B + 2 * A8_B)
#define OFF_B8H (2 * ABF_B + 3 * A8_B)
#define STAGE_B (2 * ABF_B + 4 * A8_B)  // 45056
#define NSTG 3

// chunk = k32 slab of all 6 tiles
template <int MODE>
__device__ __forceinline__ void issue_chunk(uint32_t sbase, int stage, int chunk,
                                            int m0, int n0, int tid) {
    const __nv_bfloat16 *Ah, *Bh;
    const uint8_t *A8h, *A8l, *B8l, *B8h;
    int sA, sB, rA, rB, kcol;
    if (MODE == 1 && chunk >= 128) {
        kcol = (chunk - 128) * 32;
        Ah = g_ghi;  A8h = g_g8h;  A8l = g_g8l;  sA = KLORA; rA = m0;
        Bh = g_Bchi; B8l = g_Bc8l; B8h = g_Bc8h; sB = KLORA; rB = n0;
    } else if (MODE == 1) {
        kcol = chunk * 32;
        Ah = g_xhi; A8h = g_xa8h; A8l = g_xa8l; sA = DIM; rA = m0;
        Bh = g_Whi; B8l = g_Wb8l; B8h = g_Wb8h; sB = DIM; rB = n0;
    } else {
        kcol = chunk * 32;
        Ah = g_xhi; A8h = g_xa8h; A8l = g_xa8l; sA = DIM; rA = m0;
        Bh = g_Ahi; B8l = g_Ab8l; B8h = g_Ab8h; sB = DIM; rB = 0;
    }
    uint32_t base = sbase + stage * STAGE_B;
    // bf16 tiles: 512 x 16B each
#pragma unroll
    for (int part = 0; part < 2; part++) {
        int idx = tid + part * 256;
        int row = idx >> 2, k16 = idx & 3;
        uint32_t dof = row * RS + k16 * 16;
        cp16(base + OFF_ABF + dof, Ah + (size_t)(rA + row) * sA + kcol + k16 * 8);
        cp16(base + OFF_BBF + dof, Bh + (size_t)(rB + row) * sB + kcol + k16 * 8);
    }
    // fp8 tiles: 256 x 16B each
    {
        int row = tid >> 1, half = tid & 1;
        uint32_t dof = row * RS8 + half * 16;
        size_t oa = (size_t)(rA + row) * sA + kcol + half * 16;
        size_t ob = (size_t)(rB + row) * sB + kcol + half * 16;
        cp16(base + OFF_A8H + dof, A8h + oa);
        cp16(base + OFF_A8L + dof, A8l + oa);
        cp16(base + OFF_B8L + dof, B8l + ob);
        cp16(base + OFF_B8H + dof, B8h + ob);
    }
}

__device__ __forceinline__ void compute_stage(uint32_t sbase, int stage, int wm, int wn,
                                              uint32_t aLane, uint32_t bLane,
                                              uint32_t a8Lane, uint32_t b8Lane,
                                              float acc[4][4][4], float acc8[4][4][4]) {
    uint32_t base = sbase + stage * STAGE_B;
    // ---- bf16 hh pass (2 x k16) ----
    uint32_t aB = base + OFF_ABF + wm * 64 * RS + aLane;
    uint32_t bB = base + OFF_BBF + wn * RS + bLane;
#pragma unroll
    for (int s = 0; s < 2; s++) {
        uint32_t ah[4][4];
#pragma unroll
        for (int mt = 0; mt < 4; mt++)
            ldsm4(ah[mt][0], ah[mt][1], ah[mt][2], ah[mt][3], aB + mt * 16 * RS + s * 32);
        uint32_t bh[4][2];
#pragma unroll
        for (int p = 0; p < 2; p++)
            ldsm4(bh[2 * p][0], bh[2 * p][1], bh[2 * p + 1][0], bh[2 * p + 1][1],
                  bB + p * 16 * RS + s * 32);
#pragma unroll
        for (int mt = 0; mt < 4; mt++)
#pragma unroll
            for (int nt = 0; nt < 4; nt++)
                mma16816(acc[mt][nt], ah[mt], bh[nt]);
    }
    // ---- fp8 correction pass (k32): ah*bl' + al'*bh' ----
    uint32_t a8hB = base + OFF_A8H + wm * 64 * RS8 + a8Lane;
    uint32_t a8lB = base + OFF_A8L + wm * 64 * RS8 + a8Lane;
    uint32_t b8lB = base + OFF_B8L + wn * RS8 + b8Lane;
    uint32_t b8hB = base + OFF_B8H + wn * RS8 + b8Lane;
    uint32_t bl8[4][2], bh8[4][2];
#pragma unroll
    for (int p = 0; p < 2; p++) {
        ldsm4(bl8[2 * p][0], bl8[2 * p][1], bl8[2 * p + 1][0], bl8[2 * p + 1][1],
              b8lB + p * 16 * RS8);
        ldsm4(bh8[2 * p][0], bh8[2 * p][1], bh8[2 * p + 1][0], bh8[2 * p + 1][1],
              b8hB + p * 16 * RS8);
    }
#pragma unroll
    for (int mt = 0; mt < 4; mt++) {
        uint32_t ah8[4], al8[4];
        ldsm4(ah8[0], ah8[1], ah8[2], ah8[3], a8hB + mt * 16 * RS8);
        ldsm4(al8[0], al8[1], al8[2], al8[3], a8lB + mt * 16 * RS8);
#pragma unroll
        for (int nt = 0; nt < 4; nt++) {
            mma8(acc8[mt][nt], ah8, bl8[nt]);
            mma8(acc8[mt][nt], al8, bh8[nt]);
        }
    }
}

// MODE 0: h-gemm; MODE 1: main GEMM (128 chunks x/W + 4 chunks g/Bc)
template <int MODE>
__global__ __launch_bounds__(256, 1)
void hmma_gemm_kernel(const float* __restrict__ bb, float* __restrict__ out) {
    constexpr int NCHUNK = (MODE == 1) ? 132 : 128;
    extern __shared__ char smem[];
    uint32_t sbase = smem_u32(smem);

    int tid = threadIdx.x;
    int wid = tid >> 5, lane = tid & 31;
    int wm = wid >> 2;
    int wn = (wid & 3) * 32;

    int m0, n0;
    if (MODE == 1) {
        int bid = blockIdx.x;
        int idx = bid & 255;
        int mg = (bid >> 8) & 3;
        int ng = bid >> 10;
        m0 = (mg * 16 + (idx & 15)) * 128;
        n0 = (ng * 16 + (idx >> 4)) * 128;
    } else {
        m0 = blockIdx.x * 128; n0 = 0;
    }

    uint32_t aLane = (uint32_t)((lane & 15) * RS + (lane >> 4) * 16);
    uint32_t bLane = (uint32_t)(((lane & 7) + ((lane >> 4) & 1) * 8) * RS + ((lane >> 3) & 1) * 16);
    uint32_t a8Lane = (uint32_t)((lane & 15) * RS8 + (lane >> 4) * 16);
    uint32_t b8Lane = (uint32_t)((lane & 7) * RS8 + ((lane >> 3) & 1) * 16 + ((lane >> 4) & 1) * 8 * RS8);

    float acc[4][4][4], acc8[4][4][4];
#pragma unroll
    for (int a = 0; a < 4; a++)
#pragma unroll
        for (int b = 0; b < 4; b++)
#pragma unroll
            for (int c = 0; c < 4; c++) { acc[a][b][c] = 0.f; acc8[a][b][c] = 0.f; }

    issue_chunk<MODE>(sbase, 0, 0, m0, n0, tid); CP_COMMIT();
    issue_chunk<MODE>(sbase, 1, 1, m0, n0, tid); CP_COMMIT();

#pragma unroll 1
    for (int i = 0; i < NCHUNK; i++) {
        CP_WAIT1();
        __syncthreads();
        if (i + 2 < NCHUNK)
            issue_chunk<MODE>(sbase, (i + 2) % NSTG, i + 2, m0, n0, tid);
        CP_COMMIT();
        compute_stage(sbase, i % NSTG, wm, wn, aLane, bLane, a8Lane, b8Lane, acc, acc8);
    }

    // ---- epilogue ----
    int g = lane >> 2, t = lane & 3;
    if (MODE == 1) {
#pragma unroll
        for (int mt = 0; mt < 4; mt++) {
            int r0 = m0 + wm * 64 + mt * 16 + g;
#pragma unroll
            for (int nt = 0; nt < 4; nt++) {
                int cc = n0 + wn + nt * 8 + t * 2;
                float2 bv = *(const float2*)(bb + cc);
                float2 v0, v1;
                v0.x = acc[mt][nt][0] + acc8[mt][nt][0] * INV_S + bv.x;
                v0.y = acc[mt][nt][1] + acc8[mt][nt][1] * INV_S + bv.y;
                v1.x = acc[mt][nt][2] + acc8[mt][nt][2] * INV_S + bv.x;
                v1.y = acc[mt][nt][3] + acc8[mt][nt][3] * INV_S + bv.y;
                *(float2*)(out + (size_t)r0 * ODIM + cc) = v0;
                *(float2*)(out + (size_t)(r0 + 8) * ODIM + cc) = v1;
            }
        }
    } else {
#pragma unroll
        for (int mt = 0; mt < 4; mt++) {
            int r0 = m0 + wm * 64 + mt * 16 + g;
            int r1 = r0 + 8;
#pragma unroll
            for (int nt = 0; nt < 4; nt++) {
                int cc = wn + nt * 8 + t * 2;
                int e = (wn + nt * 8) >> 4;
                float w0 = g_w[r0 * NEXP + e];
                float w1 = g_w[r1 * NEXP + e];
                float vals[2][2] = {
                    { (acc[mt][nt][0] + acc8[mt][nt][0] * INV_S) * w0,
                      (acc[mt][nt][1] + acc8[mt][nt][1] * INV_S) * w0 },
                    { (acc[mt][nt][2] + acc8[mt][nt][2] * INV_S) * w1,
                      (acc[mt][nt][3] + acc8[mt][nt][3] * INV_S) * w1 } };
                int rows[2] = {r0, r1};
#pragma unroll
                for (int q = 0; q < 2; q++) {
                    __nv_bfloat16 h0 = __float2bfloat16(vals[q][0]);
                    __nv_bfloat16 h1 = __float2bfloat16(vals[q][1]);
                    float hf0 = __bfloat162float(h0), hf1 = __bfloat162float(h1);
                    size_t o = (size_t)rows[q] * KLORA + cc;
                    *(__nv_bfloat162*)(g_ghi + o) = __nv_bfloat162(h0, h1);
                    g_g8h[o]     = to_e4m3(hf0);
                    g_g8h[o + 1] = to_e4m3(hf1);
                    g_g8l[o]     = to_e4m3((vals[q][0] - hf0) * S_AL);
                    g_g8l[o + 1] = to_e4m3((vals[q][1] - hf1) * S_AL);
                }
            }
        }
    }
}

// ---------------------------------------------------------------------------
extern "C" void kernel_launch(void* const* d_in, const int* in_sizes, int n_in,
                              void* d_out, int out_size) {
    const float* x  = (const float*)d_in[0];
    const float* Wb = (const float*)d_in[1];
    const float* bb = (const float*)d_in[2];
    const float* Wg = (const float*)d_in[3];
    const float* Wt = (const float*)d_in[4];
    const float* bt = (const float*)d_in[5];
    const float* Aw = (const float*)d_in[6];
    const float* Bw = (const float*)d_in[7];
    float* out = (float*)d_out;

    constexpr int SMEM_GEMM = NSTG * STAGE_B;   // 135168
    cudaFuncSetAttribute(hmma_gemm_kernel<0>, cudaFuncAttributeMaxDynamicSharedMemorySize, SMEM_GEMM);
    cudaFuncSetAttribute(hmma_gemm_kernel<1>, cudaFuncAttributeMaxDynamicSharedMemorySize, SMEM_GEMM);

    { int n4 = NTOK * DIM / 4;  split_kernel<<<(n4 + 255) / 256, 256>>>(x, 0, n4); }
    { int n4 = ODIM * DIM / 4;  split_kernel<<<(n4 + 255) / 256, 256>>>(Wb, 1, n4); }
    { int n4 = KLORA * DIM / 4; split_kernel<<<(n4 + 255) / 256, 256>>>(Aw, 2, n4); }
    build_bc_kernel<<<(ODIM * KLORA + 255) / 256, 256>>>(Bw);
    gate_kernel<<<NTOK / GT, 256>>>(x, Wg, Wt, bt);

    hmma_gemm_kernel<0><<<NTOK / 128, 256, SMEM_GEMM>>>(nullptr, nullptr);
    hmma_gemm_kernel<1><<<(NTOK / 128) * (ODIM / 128), 256, SMEM_GEMM>>>(bb, out);
}

// round 5
// speedup vs baseline: 1.3545x; 1.3545x over previous
#include <cuda_runtime.h>
#include <cuda_bf16.h>
#include <cstdint>

#define NTOK 8192
#define DIM 4096
#define ODIM 4096
#define NEXP 8
#define RNK 16
#define KLORA 128
#define SCALING_F 2.0f
#define MAXTHR 0.125f

// ---------------- device scratch --------------------------------------------
__device__ float g_w[NTOK * NEXP];
__device__ __nv_bfloat16 g_xhi[(size_t)NTOK * DIM];
__device__ __nv_bfloat16 g_xlo[(size_t)NTOK * DIM];
__device__ __nv_bfloat16 g_Whi[(size_t)ODIM * DIM];
__device__ __nv_bfloat16 g_Wlo[(size_t)ODIM * DIM];
__device__ __nv_bfloat16 g_Ahi[KLORA * DIM];
__device__ __nv_bfloat16 g_Alo[KLORA * DIM];
__device__ __nv_bfloat16 g_Bchi[ODIM * KLORA];
__device__ __nv_bfloat16 g_Bclo[ODIM * KLORA];
__device__ __nv_bfloat16 g_ghi[NTOK * KLORA];
__device__ __nv_bfloat16 g_glo[NTOK * KLORA];

// ---------------- PTX helpers -----------------------------------------------
__device__ __forceinline__ uint32_t smem_u32(const void* p) {
    uint32_t a;
    asm("{ .reg .u64 t; cvta.to.shared.u64 t, %1; cvt.u32.u64 %0, t; }" : "=r"(a) : "l"(p));
    return a;
}
__device__ __forceinline__ void cp16(uint32_t dst, const void* src) {
    asm volatile("cp.async.cg.shared.global [%0], [%1], 16;" :: "r"(dst), "l"(src));
}
#define CP_COMMIT() asm volatile("cp.async.commit_group;" ::: "memory")
#define CP_WAIT1()  asm volatile("cp.async.wait_group 1;" ::: "memory")

__device__ __forceinline__ void ldsm4(uint32_t& r0, uint32_t& r1, uint32_t& r2, uint32_t& r3,
                                      uint32_t addr) {
    asm volatile("ldmatrix.sync.aligned.m8n8.x4.shared.b16 {%0,%1,%2,%3}, [%4];"
                 : "=r"(r0), "=r"(r1), "=r"(r2), "=r"(r3) : "r"(addr));
}
__device__ __forceinline__ void mma16816(float* d, const uint32_t* a, const uint32_t* b) {
    asm volatile("mma.sync.aligned.m16n8k16.row.col.f32.bf16.bf16.f32 "
                 "{%0,%1,%2,%3}, {%4,%5,%6,%7}, {%8,%9}, {%0,%1,%2,%3};"
                 : "+f"(d[0]), "+f"(d[1]), "+f"(d[2]), "+f"(d[3])
                 : "r"(a[0]), "r"(a[1]), "r"(a[2]), "r"(a[3]), "r"(b[0]), "r"(b[1]));
}

// ---------------- split helpers ---------------------------------------------
__device__ __forceinline__ void split1(float v, __nv_bfloat16& h, __nv_bfloat16& l) {
    h = __float2bfloat16(v);
    l = __float2bfloat16(v - __bfloat162float(h));
}
__global__ void split_kernel(const float* __restrict__ src, int which, int n4) {
    __nv_bfloat16 *hi, *lo;
    if (which == 0)      { hi = g_xhi; lo = g_xlo; }
    else if (which == 1) { hi = g_Whi; lo = g_Wlo; }
    else                 { hi = g_Ahi; lo = g_Alo; }
    int i = blockIdx.x * blockDim.x + threadIdx.x;
    if (i >= n4) return;
    float4 v = ((const float4*)src)[i];
    __nv_bfloat16 h0, h1, h2, h3, l0, l1, l2, l3;
    split1(v.x, h0, l0); split1(v.y, h1, l1); split1(v.z, h2, l2); split1(v.w, h3, l3);
    ((__nv_bfloat162*)hi)[2 * i]     = __nv_bfloat162(h0, h1);
    ((__nv_bfloat162*)hi)[2 * i + 1] = __nv_bfloat162(h2, h3);
    ((__nv_bfloat162*)lo)[2 * i]     = __nv_bfloat162(l0, l1);
    ((__nv_bfloat162*)lo)[2 * i + 1] = __nv_bfloat162(l2, l3);
}
__global__ void build_bc_kernel(const float* __restrict__ Bw) {
    int idx = blockIdx.x * blockDim.x + threadIdx.x;
    if (idx >= ODIM * KLORA) return;
    int o = idx >> 7, k = idx & 127;
    int e = k >> 4, r = k & 15;
    float v = Bw[((size_t)e * ODIM + o) * RNK + r];
    __nv_bfloat16 h, l; split1(v, h, l);
    g_Bchi[idx] = h; g_Bclo[idx] = l;
}

// ---------------- gate kernel -----------------------------------------------
#define GT 4
__global__ void gate_kernel(const float* __restrict__ x,
                            const float* __restrict__ Wg,
                            const float* __restrict__ Wt,
                            const float* __restrict__ bt) {
    int n0 = blockIdx.x * GT;
    int tid = threadIdx.x;
    float acc[GT][9];
#pragma unroll
    for (int t = 0; t < GT; t++)
#pragma unroll
        for (int i = 0; i < 9; i++) acc[t][i] = 0.f;
    for (int d = tid; d < DIM; d += 256) {
        float wv[9];
#pragma unroll
        for (int e = 0; e < NEXP; e++) wv[e] = Wg[e * DIM + d];
        wv[8] = Wt[d];
#pragma unroll
        for (int t = 0; t < GT; t++) {
            float xv = x[(size_t)(n0 + t) * DIM + d];
#pragma unroll
            for (int i = 0; i < 9; i++) acc[t][i] = fmaf(xv, wv[i], acc[t][i]);
        }
    }
#pragma unroll
    for (int t = 0; t < GT; t++)
#pragma unroll
        for (int i = 0; i < 9; i++)
#pragma unroll
            for (int off = 16; off; off >>= 1)
                acc[t][i] += __shfl_down_sync(0xffffffffu, acc[t][i], off);
    __shared__ float sred[8][GT][9];
    int warp = tid >> 5, lane = tid & 31;
    if (lane == 0)
#pragma unroll
        for (int t = 0; t < GT; t++)
#pragma unroll
            for (int i = 0; i < 9; i++) sred[warp][t][i] = acc[t][i];
    __syncthreads();
    if (tid < GT) {
        int t = tid;
        float v[9];
#pragma unroll
        for (int i = 0; i < 9; i++) {
            float s = 0.f;
#pragma unroll
            for (int w2 = 0; w2 < 8; w2++) s += sred[w2][t][i];
            v[i] = s;
        }
        float mx = v[0];
#pragma unroll
        for (int e = 1; e < NEXP; e++) mx = fmaxf(mx, v[e]);
        float se = 0.f, gate[NEXP];
#pragma unroll
        for (int e = 0; e < NEXP; e++) { gate[e] = expf(v[e] - mx); se += gate[e]; }
        float inv = 1.f / se;
        float thr = MAXTHR / (1.f + expf(-(v[8] + bt[0])));
        float w[NEXP]; float ws = 0.f;
#pragma unroll
        for (int e = 0; e < NEXP; e++) {
            float a = gate[e] * inv - thr;
            w[e] = (a >= 0.f) ? a : 0.f;
            ws += w[e];
        }
        if (ws == 0.f) ws = 1.f;
        float sc = SCALING_F / ws;
#pragma unroll
        for (int e = 0; e < NEXP; e++) g_w[(n0 + t) * NEXP + e] = w[e] * sc;
    }
}

// ---------------- HMMA GEMM --------------------------------------------------
// smem tile rows of 32 bf16 (64B), row stride 80B => conflict-free ldmatrix
#define RS 80
#define A_B (128 * RS)                 // 10240 B per A tile
#define NSTG 3

// MODE 0: h-gemm, BN=128, NT=128 (4 warps). MODE 1: main, BN=256, NT=256 (8 warps).
template <int MODE, int BN, int NT>
__device__ __forceinline__ void issue_chunk(uint32_t sbase, int stage, int chunk,
                                            int m0, int n0, int tid) {
    constexpr int B_B = BN * RS;
    constexpr int STAGE_B = 2 * A_B + 2 * B_B;
    const __nv_bfloat16 *Ah, *Al, *Bh, *Bl;
    int sA, sB, rA, rB, kcol;
    if (MODE == 1 && chunk >= 128) {
        kcol = (chunk - 128) * 32;
        Ah = g_ghi;  Al = g_glo;  sA = KLORA; rA = m0;
        Bh = g_Bchi; Bl = g_Bclo; sB = KLORA; rB = n0;
    } else if (MODE == 1) {
        kcol = chunk * 32;
        Ah = g_xhi; Al = g_xlo; sA = DIM; rA = m0;
        Bh = g_Whi; Bl = g_Wlo; sB = DIM; rB = n0;
    } else {
        kcol = chunk * 32;
        Ah = g_xhi; Al = g_xlo; sA = DIM; rA = m0;
        Bh = g_Ahi; Bl = g_Alo; sB = DIM; rB = 0;
    }
    uint32_t base = sbase + stage * STAGE_B;
#pragma unroll
    for (int c = tid; c < 128 * 4; c += NT) {
        int row = c >> 2, k16 = c & 3;
        uint32_t dof = row * RS + k16 * 16;
        size_t off = (size_t)(rA + row) * sA + kcol + k16 * 8;
        cp16(base + dof, Ah + off);
        cp16(base + A_B + dof, Al + off);
    }
#pragma unroll
    for (int c = tid; c < BN * 4; c += NT) {
        int row = c >> 2, k16 = c & 3;
        uint32_t dof = row * RS + k16 * 16;
        size_t off = (size_t)(rB + row) * sB + kcol + k16 * 8;
        cp16(base + 2 * A_B + dof, Bh + off);
        cp16(base + 2 * A_B + B_B + dof, Bl + off);
    }
}

// warp tile 64x64: acc[4][8][4]
template <int BN>
__device__ __forceinline__ void compute_stage(uint32_t sbase, int stage, int wm, int wn64,
                                              uint32_t aLane, uint32_t bLane,
                                              float acc[4][8][4]) {
    constexpr int B_B = BN * RS;
    constexpr int STAGE_B = 2 * A_B + 2 * B_B;
    uint32_t base = sbase + stage * STAGE_B;
    uint32_t aHiB = base + wm * 64 * RS + aLane;
    uint32_t bHiB = base + 2 * A_B + wn64 * 64 * RS + bLane;
#pragma unroll
    for (int s = 0; s < 2; s++) {
        uint32_t ah[4][4], bh[8][2], bl[8][2];
#pragma unroll
        for (int mt = 0; mt < 4; mt++)
            ldsm4(ah[mt][0], ah[mt][1], ah[mt][2], ah[mt][3], aHiB + mt * 16 * RS + s * 32);
#pragma unroll
        for (int p = 0; p < 4; p++)
            ldsm4(bh[2 * p][0], bh[2 * p][1], bh[2 * p + 1][0], bh[2 * p + 1][1],
                  bHiB + p * 16 * RS + s * 32);
        // pass 1: ah * bh
#pragma unroll
        for (int mt = 0; mt < 4; mt++)
#pragma unroll
            for (int nt = 0; nt < 8; nt++) mma16816(acc[mt][nt], ah[mt], bh[nt]);
        // pass 2: ah * bl
#pragma unroll
        for (int p = 0; p < 4; p++)
            ldsm4(bl[2 * p][0], bl[2 * p][1], bl[2 * p + 1][0], bl[2 * p + 1][1],
                  bHiB + B_B + p * 16 * RS + s * 32);
#pragma unroll
        for (int mt = 0; mt < 4; mt++)
#pragma unroll
            for (int nt = 0; nt < 8; nt++) mma16816(acc[mt][nt], ah[mt], bl[nt]);
        // pass 3: al * bh (al overwrites ah)
#pragma unroll
        for (int mt = 0; mt < 4; mt++)
            ldsm4(ah[mt][0], ah[mt][1], ah[mt][2], ah[mt][3],
                  aHiB + A_B + mt * 16 * RS + s * 32);
#pragma unroll
        for (int mt = 0; mt < 4; mt++)
#pragma unroll
            for (int nt = 0; nt < 8; nt++) mma16816(acc[mt][nt], ah[mt], bh[nt]);
    }
}

template <int MODE, int BN, int NT>
__global__ __launch_bounds__(NT, 1)
void hmma_gemm_kernel(const float* __restrict__ bb, float* __restrict__ out) {
    constexpr int NCHUNK = (MODE == 1) ? 132 : 128;
    extern __shared__ char smem[];
    uint32_t sbase = smem_u32(smem);

    int tid = threadIdx.x;
    int wid = tid >> 5, lane = tid & 31;
    int wm = wid & 1;            // 64-row slab
    int wn64 = wid >> 1;         // 64-col slab

    int m0, n0;
    if (MODE == 1) {
        int bid = blockIdx.x;
        int sg = bid >> 6, idx = bid & 63;      // 8x8 supergroups
        int mg = sg & 7, ng = sg >> 3;
        m0 = (mg * 8 + (idx & 7)) * 128;
        n0 = (ng * 8 + (idx >> 3)) * 256;
    } else {
        m0 = blockIdx.x * 128; n0 = 0;
    }

    uint32_t aLane = (uint32_t)((lane & 15) * RS + (lane >> 4) * 16);
    uint32_t bLane = (uint32_t)(((lane & 7) + ((lane >> 4) & 1) * 8) * RS + ((lane >> 3) & 1) * 16);

    float acc[4][8][4];
#pragma unroll
    for (int a = 0; a < 4; a++)
#pragma unroll
        for (int b = 0; b < 8; b++)
#pragma unroll
            for (int c = 0; c < 4; c++) acc[a][b][c] = 0.f;

    issue_chunk<MODE, BN, NT>(sbase, 0, 0, m0, n0, tid); CP_COMMIT();
    issue_chunk<MODE, BN, NT>(sbase, 1, 1, m0, n0, tid); CP_COMMIT();

#pragma unroll 1
    for (int i = 0; i < NCHUNK; i++) {
        CP_WAIT1();
        __syncthreads();
        if (i + 2 < NCHUNK)
            issue_chunk<MODE, BN, NT>(sbase, (i + 2) % NSTG, i + 2, m0, n0, tid);
        CP_COMMIT();
        compute_stage<BN>(sbase, i % NSTG, wm, wn64, aLane, bLane, acc);
    }

    // ---- epilogue ----
    int g = lane >> 2, t = lane & 3;
    if (MODE == 1) {
#pragma unroll
        for (int mt = 0; mt < 4; mt++) {
            int r0 = m0 + wm * 64 + mt * 16 + g;
#pragma unroll
            for (int nt = 0; nt < 8; nt++) {
                int cc = n0 + wn64 * 64 + nt * 8 + t * 2;
                float2 bv = *(const float2*)(bb + cc);
                float2 v0 = make_float2(acc[mt][nt][0] + bv.x, acc[mt][nt][1] + bv.y);
                float2 v1 = make_float2(acc[mt][nt][2] + bv.x, acc[mt][nt][3] + bv.y);
                *(float2*)(out + (size_t)r0 * ODIM + cc) = v0;
                *(float2*)(out + (size_t)(r0 + 8) * ODIM + cc) = v1;
            }
        }
    } else {
#pragma unroll
        for (int mt = 0; mt < 4; mt++) {
            int r0 = m0 + wm * 64 + mt * 16 + g;
            int r1 = r0 + 8;
#pragma unroll
            for (int nt = 0; nt < 8; nt++) {
                int cc = wn64 * 64 + nt * 8 + t * 2;
                int e = (wn64 * 64 + nt * 8) >> 4;
                float w0 = g_w[r0 * NEXP + e];
                float w1 = g_w[r1 * NEXP + e];
                float v00 = acc[mt][nt][0] * w0, v01 = acc[mt][nt][1] * w0;
                float v10 = acc[mt][nt][2] * w1, v11 = acc[mt][nt][3] * w1;
                __nv_bfloat16 h0, l0, h1, l1;
                split1(v00, h0, l0); split1(v01, h1, l1);
                *(__nv_bfloat162*)(g_ghi + (size_t)r0 * KLORA + cc) = __nv_bfloat162(h0, h1);
                *(__nv_bfloat162*)(g_glo + (size_t)r0 * KLORA + cc) = __nv_bfloat162(l0, l1);
                split1(v10, h0, l0); split1(v11, h1, l1);
                *(__nv_bfloat162*)(g_ghi + (size_t)r1 * KLORA + cc) = __nv_bfloat162(h0, h1);
                *(__nv_bfloat162*)(g_glo + (size_t)r1 * KLORA + cc) = __nv_bfloat162(l0, l1);
            }
        }
    }
}

// ---------------------------------------------------------------------------
extern "C" void kernel_launch(void* const* d_in, const int* in_sizes, int n_in,
                              void* d_out, int out_size) {
    const float* x  = (const float*)d_in[0];
    const float* Wb = (const float*)d_in[1];
    const float* bb = (const float*)d_in[2];
    const float* Wg = (const float*)d_in[3];
    const float* Wt = (const float*)d_in[4];
    const float* bt = (const float*)d_in[5];
    const float* Aw = (const float*)d_in[6];
    const float* Bw = (const float*)d_in[7];
    float* out = (float*)d_out;

    constexpr int SMEM_MAIN = NSTG * (2 * A_B + 2 * 256 * RS);  // 184320
    constexpr int SMEM_H    = NSTG * (2 * A_B + 2 * 128 * RS);  // 122880
    cudaFuncSetAttribute(hmma_gemm_kernel<1, 256, 256>, cudaFuncAttributeMaxDynamicSharedMemorySize, SMEM_MAIN);
    cudaFuncSetAttribute(hmma_gemm_kernel<0, 128, 128>, cudaFuncAttributeMaxDynamicSharedMemorySize, SMEM_H);

    { int n4 = NTOK * DIM / 4;  split_kernel<<<(n4 + 255) / 256, 256>>>(x, 0, n4); }
    { int n4 = ODIM * DIM / 4;  split_kernel<<<(n4 + 255) / 256, 256>>>(Wb, 1, n4); }
    { int n4 = KLORA * DIM / 4; split_kernel<<<(n4 + 255) / 256, 256>>>(Aw, 2, n4); }
    build_bc_kernel<<<(ODIM * KLORA + 255) / 256, 256>>>(Bw);
    gate_kernel<<<NTOK / GT, 256>>>(x, Wg, Wt, bt);

    hmma_gemm_kernel<0, 128, 128><<<NTOK / 128, 128, SMEM_H>>>(nullptr, nullptr);
    hmma_gemm_kernel<1, 256, 256><<<(NTOK / 128) * (ODIM / 256), 256, SMEM_MAIN>>>(bb, out);
}

// round 6
// speedup vs baseline: 1.9129x; 1.4123x over previous
#include <cuda_runtime.h>
#include <cuda_fp16.h>
#include <cstdint>

#define NTOK 8192
#define DIM 4096
#define ODIM 4096
#define NEXP 8
#define RNK 16
#define KLORA 128
#define SCALING_F 2.0f
#define MAXTHR 0.125f

// ---------------- device scratch --------------------------------------------
__device__ float g_w[NTOK * NEXP];
__device__ __half g_xhi[(size_t)NTOK * DIM];
__device__ __half g_xlo[(size_t)NTOK * DIM];
__device__ __half g_Wh[(size_t)ODIM * DIM];
__device__ __half g_Ah[KLORA * DIM];
__device__ __half g_Bc[ODIM * KLORA];
__device__ __half g_ghi[NTOK * KLORA];
__device__ __half g_glo[NTOK * KLORA];

// ---------------- PTX helpers -----------------------------------------------
__device__ __forceinline__ uint32_t smem_u32(const void* p) {
    uint32_t a;
    asm("{ .reg .u64 t; cvta.to.shared.u64 t, %1; cvt.u32.u64 %0, t; }" : "=r"(a) : "l"(p));
    return a;
}
__device__ __forceinline__ void cp16(uint32_t dst, const void* src) {
    asm volatile("cp.async.cg.shared.global [%0], [%1], 16;" :: "r"(dst), "l"(src));
}
#define CP_COMMIT() asm volatile("cp.async.commit_group;" ::: "memory")
#define CP_WAIT1()  asm volatile("cp.async.wait_group 1;" ::: "memory")

__device__ __forceinline__ void ldsm4(uint32_t& r0, uint32_t& r1, uint32_t& r2, uint32_t& r3,
                                      uint32_t addr) {
    asm volatile("ldmatrix.sync.aligned.m8n8.x4.shared.b16 {%0,%1,%2,%3}, [%4];"
                 : "=r"(r0), "=r"(r1), "=r"(r2), "=r"(r3) : "r"(addr));
}
__device__ __forceinline__ void mma16816(float* d, const uint32_t* a, const uint32_t* b) {
    asm volatile("mma.sync.aligned.m16n8k16.row.col.f32.f16.f16.f32 "
                 "{%0,%1,%2,%3}, {%4,%5,%6,%7}, {%8,%9}, {%0,%1,%2,%3};"
                 : "+f"(d[0]), "+f"(d[1]), "+f"(d[2]), "+f"(d[3])
                 : "r"(a[0]), "r"(a[1]), "r"(a[2]), "r"(a[3]), "r"(b[0]), "r"(b[1]));
}

// ---------------- split helpers ---------------------------------------------
__device__ __forceinline__ void split1(float v, __half& h, __half& l) {
    h = __float2half_rn(v);
    l = __float2half_rn(v - __half2float(h));
}
// which 0: x -> split-2 fp16 (xhi, xlo). which 1: W -> single fp16. which 2: A_w -> single fp16.
__global__ void split_kernel(const float* __restrict__ src, int which, int n4) {
    int i = blockIdx.x * blockDim.x + threadIdx.x;
    if (i >= n4) return;
    float4 v = ((const float4*)src)[i];
    if (which == 0) {
        __half h0, h1, h2, h3, l0, l1, l2, l3;
        split1(v.x, h0, l0); split1(v.y, h1, l1); split1(v.z, h2, l2); split1(v.w, h3, l3);
        ((__half2*)g_xhi)[2 * i]     = __half2(h0, h1);
        ((__half2*)g_xhi)[2 * i + 1] = __half2(h2, h3);
        ((__half2*)g_xlo)[2 * i]     = __half2(l0, l1);
        ((__half2*)g_xlo)[2 * i + 1] = __half2(l2, l3);
    } else {
        __half* dst = (which == 1) ? g_Wh : g_Ah;
        ((__half2*)dst)[2 * i]     = __half2(__float2half_rn(v.x), __float2half_rn(v.y));
        ((__half2*)dst)[2 * i + 1] = __half2(__float2half_rn(v.z), __float2half_rn(v.w));
    }
}
__global__ void build_bc_kernel(const float* __restrict__ Bw) {
    int idx = blockIdx.x * blockDim.x + threadIdx.x;
    if (idx >= ODIM * KLORA) return;
    int o = idx >> 7, k = idx & 127;
    int e = k >> 4, r = k & 15;
    g_Bc[idx] = __float2half_rn(Bw[((size_t)e * ODIM + o) * RNK + r]);
}

// ---------------- gate kernel -----------------------------------------------
#define GT 4
__global__ void gate_kernel(const float* __restrict__ x,
                            const float* __restrict__ Wg,
                            const float* __restrict__ Wt,
                            const float* __restrict__ bt) {
    int n0 = blockIdx.x * GT;
    int tid = threadIdx.x;
    float acc[GT][9];
#pragma unroll
    for (int t = 0; t < GT; t++)
#pragma unroll
        for (int i = 0; i < 9; i++) acc[t][i] = 0.f;
    for (int d = tid; d < DIM; d += 256) {
        float wv[9];
#pragma unroll
        for (int e = 0; e < NEXP; e++) wv[e] = Wg[e * DIM + d];
        wv[8] = Wt[d];
#pragma unroll
        for (int t = 0; t < GT; t++) {
            float xv = x[(size_t)(n0 + t) * DIM + d];
#pragma unroll
            for (int i = 0; i < 9; i++) acc[t][i] = fmaf(xv, wv[i], acc[t][i]);
        }
    }
#pragma unroll
    for (int t = 0; t < GT; t++)
#pragma unroll
        for (int i = 0; i < 9; i++)
#pragma unroll
            for (int off = 16; off; off >>= 1)
                acc[t][i] += __shfl_down_sync(0xffffffffu, acc[t][i], off);
    __shared__ float sred[8][GT][9];
    int warp = tid >> 5, lane = tid & 31;
    if (lane == 0)
#pragma unroll
        for (int t = 0; t < GT; t++)
#pragma unroll
            for (int i = 0; i < 9; i++) sred[warp][t][i] = acc[t][i];
    __syncthreads();
    if (tid < GT) {
        int t = tid;
        float v[9];
#pragma unroll
        for (int i = 0; i < 9; i++) {
            float s = 0.f;
#pragma unroll
            for (int w2 = 0; w2 < 8; w2++) s += sred[w2][t][i];
            v[i] = s;
        }
        float mx = v[0];
#pragma unroll
        for (int e = 1; e < NEXP; e++) mx = fmaxf(mx, v[e]);
        float se = 0.f, gate[NEXP];
#pragma unroll
        for (int e = 0; e < NEXP; e++) { gate[e] = expf(v[e] - mx); se += gate[e]; }
        float inv = 1.f / se;
        float thr = MAXTHR / (1.f + expf(-(v[8] + bt[0])));
        float w[NEXP]; float ws = 0.f;
#pragma unroll
        for (int e = 0; e < NEXP; e++) {
            float a = gate[e] * inv - thr;
            w[e] = (a >= 0.f) ? a : 0.f;
            ws += w[e];
        }
        if (ws == 0.f) ws = 1.f;
        float sc = SCALING_F / ws;
#pragma unroll
        for (int e = 0; e < NEXP; e++) g_w[(n0 + t) * NEXP + e] = w[e] * sc;
    }
}

// ---------------- HMMA GEMM --------------------------------------------------
// smem tile rows of 32 fp16 (64B), row stride 80B => conflict-free ldmatrix
#define RS 80
#define A_B (128 * RS)                 // 10240 B per A tile
#define NSTG 3

// per stage: Ahi, Alo (128 rows each) + Bh (BN rows)
template <int MODE, int BN, int NT>
__device__ __forceinline__ void issue_chunk(uint32_t sbase, int stage, int chunk,
                                            int m0, int n0, int tid) {
    constexpr int B_B = BN * RS;
    constexpr int STAGE_B = 2 * A_B + B_B;
    const __half *Ahi, *Alo, *Bh;
    int sA, sB, rA, rB, kcol;
    if (MODE == 1 && chunk >= 128) {
        kcol = (chunk - 128) * 32;
        Ahi = g_ghi; Alo = g_glo; sA = KLORA; rA = m0;
        Bh = g_Bc; sB = KLORA; rB = n0;
    } else if (MODE == 1) {
        kcol = chunk * 32;
        Ahi = g_xhi; Alo = g_xlo; sA = DIM; rA = m0;
        Bh = g_Wh; sB = DIM; rB = n0;
    } else {
        kcol = chunk * 32;
        Ahi = g_xhi; Alo = g_xlo; sA = DIM; rA = m0;
        Bh = g_Ah; sB = DIM; rB = 0;
    }
    uint32_t base = sbase + stage * STAGE_B;
#pragma unroll
    for (int c = tid; c < 128 * 4; c += NT) {
        int row = c >> 2, k16 = c & 3;
        uint32_t dof = row * RS + k16 * 16;
        size_t off = (size_t)(rA + row) * sA + kcol + k16 * 8;
        cp16(base + dof, Ahi + off);
        cp16(base + A_B + dof, Alo + off);
    }
#pragma unroll
    for (int c = tid; c < BN * 4; c += NT) {
        int row = c >> 2, k16 = c & 3;
        uint32_t dof = row * RS + k16 * 16;
        cp16(base + 2 * A_B + dof, Bh + (size_t)(rB + row) * sB + kcol + k16 * 8);
    }
}

// warp tile 64x64: acc[4][8][4]; 2 passes: ah*bh, al*bh
template <int BN>
__device__ __forceinline__ void compute_stage(uint32_t sbase, int stage, int wm, int wn64,
                                              uint32_t aLane, uint32_t bLane,
                                              float acc[4][8][4]) {
    constexpr int B_B = BN * RS;
    constexpr int STAGE_B = 2 * A_B + B_B;
    uint32_t base = sbase + stage * STAGE_B;
    uint32_t aHiB = base + wm * 64 * RS + aLane;
    uint32_t bB = base + 2 * A_B + wn64 * 64 * RS + bLane;
#pragma unroll
    for (int s = 0; s < 2; s++) {
        uint32_t ah[4][4], bh[8][2];
#pragma unroll
        for (int mt = 0; mt < 4; mt++)
            ldsm4(ah[mt][0], ah[mt][1], ah[mt][2], ah[mt][3], aHiB + mt * 16 * RS + s * 32);
#pragma unroll
        for (int p = 0; p < 4; p++)
            ldsm4(bh[2 * p][0], bh[2 * p][1], bh[2 * p + 1][0], bh[2 * p + 1][1],
                  bB + p * 16 * RS + s * 32);
        // pass 1: ah * bh
#pragma unroll
        for (int mt = 0; mt < 4; mt++)
#pragma unroll
            for (int nt = 0; nt < 8; nt++) mma16816(acc[mt][nt], ah[mt], bh[nt]);
        // pass 2: al * bh (al overwrites ah)
#pragma unroll
        for (int mt = 0; mt < 4; mt++)
            ldsm4(ah[mt][0], ah[mt][1], ah[mt][2], ah[mt][3],
                  aHiB + A_B + mt * 16 * RS + s * 32);
#pragma unroll
        for (int mt = 0; mt < 4; mt++)
#pragma unroll
            for (int nt = 0; nt < 8; nt++) mma16816(acc[mt][nt], ah[mt], bh[nt]);
    }
}

template <int MODE, int BN, int NT>
__global__ __launch_bounds__(NT, 1)
void hmma_gemm_kernel(const float* __restrict__ bb, float* __restrict__ out) {
    constexpr int NCHUNK = (MODE == 1) ? 132 : 128;
    extern __shared__ char smem[];
    uint32_t sbase = smem_u32(smem);

    int tid = threadIdx.x;
    int wid = tid >> 5, lane = tid & 31;
    int wm = wid & 1;
    int wn64 = wid >> 1;

    int m0, n0;
    if (MODE == 1) {
        int bid = blockIdx.x;
        int sg = bid >> 6, idx = bid & 63;      // 8x8 supergroups
        int mg = sg & 7, ng = sg >> 3;
        m0 = (mg * 8 + (idx & 7)) * 128;
        n0 = (ng * 8 + (idx >> 3)) * 256;
    } else {
        m0 = blockIdx.x * 128; n0 = 0;
    }

    uint32_t aLane = (uint32_t)((lane & 15) * RS + (lane >> 4) * 16);
    uint32_t bLane = (uint32_t)(((lane & 7) + ((lane >> 4) & 1) * 8) * RS + ((lane >> 3) & 1) * 16);

    float acc[4][8][4];
#pragma unroll
    for (int a = 0; a < 4; a++)
#pragma unroll
        for (int b = 0; b < 8; b++)
#pragma unroll
            for (int c = 0; c < 4; c++) acc[a][b][c] = 0.f;

    issue_chunk<MODE, BN, NT>(sbase, 0, 0, m0, n0, tid); CP_COMMIT();
    issue_chunk<MODE, BN, NT>(sbase, 1, 1, m0, n0, tid); CP_COMMIT();

#pragma unroll 1
    for (int i = 0; i < NCHUNK; i++) {
        CP_WAIT1();
        __syncthreads();
        if (i + 2 < NCHUNK)
            issue_chunk<MODE, BN, NT>(sbase, (i + 2) % NSTG, i + 2, m0, n0, tid);
        CP_COMMIT();
        compute_stage<BN>(sbase, i % NSTG, wm, wn64, aLane, bLane, acc);
    }

    // ---- epilogue ----
    int g = lane >> 2, t = lane & 3;
    if (MODE == 1) {
#pragma unroll
        for (int mt = 0; mt < 4; mt++) {
            int r0 = m0 + wm * 64 + mt * 16 + g;
#pragma unroll
            for (int nt = 0; nt < 8; nt++) {
                int cc = n0 + wn64 * 64 + nt * 8 + t * 2;
                float2 bv = *(const float2*)(bb + cc);
                float2 v0 = make_float2(acc[mt][nt][0] + bv.x, acc[mt][nt][1] + bv.y);
                float2 v1 = make_float2(acc[mt][nt][2] + bv.x, acc[mt][nt][3] + bv.y);
                *(float2*)(out + (size_t)r0 * ODIM + cc) = v0;
                *(float2*)(out + (size_t)(r0 + 8) * ODIM + cc) = v1;
            }
        }
    } else {
#pragma unroll
        for (int mt = 0; mt < 4; mt++) {
            int r0 = m0 + wm * 64 + mt * 16 + g;
            int r1 = r0 + 8;
#pragma unroll
            for (int nt = 0; nt < 8; nt++) {
                int cc = wn64 * 64 + nt * 8 + t * 2;
                int e = (wn64 * 64 + nt * 8) >> 4;
                float w0 = g_w[r0 * NEXP + e];
                float w1 = g_w[r1 * NEXP + e];
                float v00 = acc[mt][nt][0] * w0, v01 = acc[mt][nt][1] * w0;
                float v10 = acc[mt][nt][2] * w1, v11 = acc[mt][nt][3] * w1;
                __half h0, l0, h1, l1;
                split1(v00, h0, l0); split1(v01, h1, l1);
                *(__half2*)(g_ghi + (size_t)r0 * KLORA + cc) = __half2(h0, h1);
                *(__half2*)(g_glo + (size_t)r0 * KLORA + cc) = __half2(l0, l1);
                split1(v10, h0, l0); split1(v11, h1, l1);
                *(__half2*)(g_ghi + (size_t)r1 * KLORA + cc) = __half2(h0, h1);
                *(__half2*)(g_glo + (size_t)r1 * KLORA + cc) = __half2(l0, l1);
            }
        }
    }
}

// ---------------------------------------------------------------------------
extern "C" void kernel_launch(void* const* d_in, const int* in_sizes, int n_in,
                              void* d_out, int out_size) {
    const float* x  = (const float*)d_in[0];
    const float* Wb = (const float*)d_in[1];
    const float* bb = (const float*)d_in[2];
    const float* Wg = (const float*)d_in[3];
    const float* Wt = (const float*)d_in[4];
    const float* bt = (const float*)d_in[5];
    const float* Aw = (const float*)d_in[6];
    const float* Bw = (const float*)d_in[7];
    float* out = (float*)d_out;

    constexpr int SMEM_MAIN = NSTG * (2 * A_B + 256 * RS);  // 122880
    constexpr int SMEM_H    = NSTG * (2 * A_B + 128 * RS);  // 92160
    cudaFuncSetAttribute(hmma_gemm_kernel<1, 256, 256>, cudaFuncAttributeMaxDynamicSharedMemorySize, SMEM_MAIN);
    cudaFuncSetAttribute(hmma_gemm_kernel<0, 128, 128>, cudaFuncAttributeMaxDynamicSharedMemorySize, SMEM_H);

    { int n4 = NTOK * DIM / 4;  split_kernel<<<(n4 + 255) / 256, 256>>>(x, 0, n4); }
    { int n4 = ODIM * DIM / 4;  split_kernel<<<(n4 + 255) / 256, 256>>>(Wb, 1, n4); }
    { int n4 = KLORA * DIM / 4; split_kernel<<<(n4 + 255) / 256, 256>>>(Aw, 2, n4); }
    build_bc_kernel<<<(ODIM * KLORA + 255) / 256, 256>>>(Bw);
    gate_kernel<<<NTOK / GT, 256>>>(x, Wg, Wt, bt);

    hmma_gemm_kernel<0, 128, 128><<<NTOK / 128, 128, SMEM_H>>>(nullptr, nullptr);
    hmma_gemm_kernel<1, 256, 256><<<(NTOK / 128) * (ODIM / 256), 256, SMEM_MAIN>>>(bb, out);
}

// round 7
// speedup vs baseline: 1.9892x; 1.0399x over previous
#include <cuda_runtime.h>
#include <cuda_fp16.h>
#include <cstdint>

#define NTOK 8192
#define DIM 4096
#define ODIM 4096
#define NEXP 8
#define RNK 16
#define KLORA 128
#define SCALING_F 2.0f
#define MAXTHR 0.125f

// ---------------- device scratch --------------------------------------------
__device__ float g_w[NTOK * NEXP];
__device__ __half g_xhi[(size_t)NTOK * DIM];
__device__ __half g_xlo[(size_t)NTOK * DIM];
__device__ __half g_Wh[(size_t)ODIM * DIM];
__device__ __half g_Ah[KLORA * DIM];
__device__ __half g_Bc[ODIM * KLORA];
__device__ __half g_ghi[NTOK * KLORA];
__device__ __half g_glo[NTOK * KLORA];

// ---------------- PTX helpers -----------------------------------------------
__device__ __forceinline__ uint32_t smem_u32(const void* p) {
    uint32_t a;
    asm("{ .reg .u64 t; cvta.to.shared.u64 t, %1; cvt.u32.u64 %0, t; }" : "=r"(a) : "l"(p));
    return a;
}
__device__ __forceinline__ void cp16(uint32_t dst, const void* src) {
    asm volatile("cp.async.cg.shared.global [%0], [%1], 16;" :: "r"(dst), "l"(src));
}
#define CP_COMMIT() asm volatile("cp.async.commit_group;" ::: "memory")
#define CP_WAIT2()  asm volatile("cp.async.wait_group 2;" ::: "memory")

__device__ __forceinline__ void ldsm4(uint32_t& r0, uint32_t& r1, uint32_t& r2, uint32_t& r3,
                                      uint32_t addr) {
    asm volatile("ldmatrix.sync.aligned.m8n8.x4.shared.b16 {%0,%1,%2,%3}, [%4];"
                 : "=r"(r0), "=r"(r1), "=r"(r2), "=r"(r3) : "r"(addr));
}
__device__ __forceinline__ void mma16816(float* d, const uint32_t* a, const uint32_t* b) {
    asm volatile("mma.sync.aligned.m16n8k16.row.col.f32.f16.f16.f32 "
                 "{%0,%1,%2,%3}, {%4,%5,%6,%7}, {%8,%9}, {%0,%1,%2,%3};"
                 : "+f"(d[0]), "+f"(d[1]), "+f"(d[2]), "+f"(d[3])
                 : "r"(a[0]), "r"(a[1]), "r"(a[2]), "r"(a[3]), "r"(b[0]), "r"(b[1]));
}

// ---------------- split helpers ---------------------------------------------
__device__ __forceinline__ void split1(float v, __half& h, __half& l) {
    h = __float2half_rn(v);
    l = __float2half_rn(v - __half2float(h));
}
// which 0: x -> split-2 fp16. which 1: W -> fp16. which 2: A_w -> fp16.
__global__ void split_kernel(const float* __restrict__ src, int which, int n4) {
    int i = blockIdx.x * blockDim.x + threadIdx.x;
    if (i >= n4) return;
    float4 v = ((const float4*)src)[i];
    if (which == 0) {
        __half h0, h1, h2, h3, l0, l1, l2, l3;
        split1(v.x, h0, l0); split1(v.y, h1, l1); split1(v.z, h2, l2); split1(v.w, h3, l3);
        ((__half2*)g_xhi)[2 * i]     = __half2(h0, h1);
        ((__half2*)g_xhi)[2 * i + 1] = __half2(h2, h3);
        ((__half2*)g_xlo)[2 * i]     = __half2(l0, l1);
        ((__half2*)g_xlo)[2 * i + 1] = __half2(l2, l3);
    } else {
        __half* dst = (which == 1) ? g_Wh : g_Ah;
        ((__half2*)dst)[2 * i]     = __half2(__float2half_rn(v.x), __float2half_rn(v.y));
        ((__half2*)dst)[2 * i + 1] = __half2(__float2half_rn(v.z), __float2half_rn(v.w));
    }
}
__global__ void build_bc_kernel(const float* __restrict__ Bw) {
    int idx = blockIdx.x * blockDim.x + threadIdx.x;
    if (idx >= ODIM * KLORA) return;
    int o = idx >> 7, k = idx & 127;
    int e = k >> 4, r = k & 15;
    g_Bc[idx] = __float2half_rn(Bw[((size_t)e * ODIM + o) * RNK + r]);
}

// ---------------- gate kernel -----------------------------------------------
#define GT 4
__global__ void gate_kernel(const float* __restrict__ x,
                            const float* __restrict__ Wg,
                            const float* __restrict__ Wt,
                            const float* __restrict__ bt) {
    int n0 = blockIdx.x * GT;
    int tid = threadIdx.x;
    float acc[GT][9];
#pragma unroll
    for (int t = 0; t < GT; t++)
#pragma unroll
        for (int i = 0; i < 9; i++) acc[t][i] = 0.f;
    for (int d = tid; d < DIM; d += 256) {
        float wv[9];
#pragma unroll
        for (int e = 0; e < NEXP; e++) wv[e] = Wg[e * DIM + d];
        wv[8] = Wt[d];
#pragma unroll
        for (int t = 0; t < GT; t++) {
            float xv = x[(size_t)(n0 + t) * DIM + d];
#pragma unroll
            for (int i = 0; i < 9; i++) acc[t][i] = fmaf(xv, wv[i], acc[t][i]);
        }
    }
#pragma unroll
    for (int t = 0; t < GT; t++)
#pragma unroll
        for (int i = 0; i < 9; i++)
#pragma unroll
            for (int off = 16; off; off >>= 1)
                acc[t][i] += __shfl_down_sync(0xffffffffu, acc[t][i], off);
    __shared__ float sred[8][GT][9];
    int warp = tid >> 5, lane = tid & 31;
    if (lane == 0)
#pragma unroll
        for (int t = 0; t < GT; t++)
#pragma unroll
            for (int i = 0; i < 9; i++) sred[warp][t][i] = acc[t][i];
    __syncthreads();
    if (tid < GT) {
        int t = tid;
        float v[9];
#pragma unroll
        for (int i = 0; i < 9; i++) {
            float s = 0.f;
#pragma unroll
            for (int w2 = 0; w2 < 8; w2++) s += sred[w2][t][i];
            v[i] = s;
        }
        float mx = v[0];
#pragma unroll
        for (int e = 1; e < NEXP; e++) mx = fmaxf(mx, v[e]);
        float se = 0.f, gate[NEXP];
#pragma unroll
        for (int e = 0; e < NEXP; e++) { gate[e] = expf(v[e] - mx); se += gate[e]; }
        float inv = 1.f / se;
        float thr = MAXTHR / (1.f + expf(-(v[8] + bt[0])));
        float w[NEXP]; float ws = 0.f;
#pragma unroll
        for (int e = 0; e < NEXP; e++) {
            float a = gate[e] * inv - thr;
            w[e] = (a >= 0.f) ? a : 0.f;
            ws += w[e];
        }
        if (ws == 0.f) ws = 1.f;
        float sc = SCALING_F / ws;
#pragma unroll
        for (int e = 0; e < NEXP; e++) g_w[(n0 + t) * NEXP + e] = w[e] * sc;
    }
}

// ---------------- HMMA GEMM --------------------------------------------------
// smem rows of 32 fp16 (64B), row stride 80B => conflict-free ldmatrix
#define RS 80
#define NSTG 4

// MODE 1: main, BM=128, BN=256, NT=256. MODE 0: h-gemm, BM=64, BN=128, NT=128.
template <int MODE, int BM, int BN, int NT>
__device__ __forceinline__ void issue_chunk(uint32_t sbase, int stage, int chunk,
                                            int m0, int n0, int tid) {
    constexpr int AB = BM * RS;
    constexpr int BB = BN * RS;
    constexpr int STAGE_B = 2 * AB + BB;
    const __half *Ahi, *Alo, *Bh;
    int sA, sB, rA, rB, kcol;
    if (MODE == 1 && chunk >= 128) {
        kcol = (chunk - 128) * 32;
        Ahi = g_ghi; Alo = g_glo; sA = KLORA; rA = m0;
        Bh = g_Bc; sB = KLORA; rB = n0;
    } else if (MODE == 1) {
        kcol = chunk * 32;
        Ahi = g_xhi; Alo = g_xlo; sA = DIM; rA = m0;
        Bh = g_Wh; sB = DIM; rB = n0;
    } else {
        kcol = chunk * 32;
        Ahi = g_xhi; Alo = g_xlo; sA = DIM; rA = m0;
        Bh = g_Ah; sB = DIM; rB = 0;
    }
    uint32_t base = sbase + stage * STAGE_B;
#pragma unroll
    for (int c = tid; c < BM * 4; c += NT) {
        int row = c >> 2, k16 = c & 3;
        uint32_t dof = row * RS + k16 * 16;
        size_t off = (size_t)(rA + row) * sA + kcol + k16 * 8;
        cp16(base + dof, Ahi + off);
        cp16(base + AB + dof, Alo + off);
    }
#pragma unroll
    for (int c = tid; c < BN * 4; c += NT) {
        int row = c >> 2, k16 = c & 3;
        uint32_t dof = row * RS + k16 * 16;
        cp16(base + 2 * AB + dof, Bh + (size_t)(rB + row) * sB + kcol + k16 * 8);
    }
}

// warp tile (MT*16) x 64; separate ah/al registers for max ILP
template <int BM, int BN, int MT>
__device__ __forceinline__ void compute_stage(uint32_t sbase, int stage, int wm, int wn64,
                                              uint32_t aLane, uint32_t bLane,
                                              float acc[MT][8][4]) {
    constexpr int AB = BM * RS;
    constexpr int BB = BN * RS;
    constexpr int STAGE_B = 2 * AB + BB;
    uint32_t base = sbase + stage * STAGE_B;
    uint32_t aHiB = base + wm * (MT * 16) * RS + aLane;
    uint32_t bB = base + 2 * AB + wn64 * 64 * RS + bLane;
#pragma unroll
    for (int s = 0; s < 2; s++) {
        uint32_t ah[MT][4], al[MT][4], bh[8][2];
#pragma unroll
        for (int mt = 0; mt < MT; mt++) {
            ldsm4(ah[mt][0], ah[mt][1], ah[mt][2], ah[mt][3], aHiB + mt * 16 * RS + s * 32);
            ldsm4(al[mt][0], al[mt][1], al[mt][2], al[mt][3],
                  aHiB + AB + mt * 16 * RS + s * 32);
        }
#pragma unroll
        for (int p = 0; p < 4; p++)
            ldsm4(bh[2 * p][0], bh[2 * p][1], bh[2 * p + 1][0], bh[2 * p + 1][1],
                  bB + p * 16 * RS + s * 32);
#pragma unroll
        for (int mt = 0; mt < MT; mt++)
#pragma unroll
            for (int nt = 0; nt < 8; nt++) {
                mma16816(acc[mt][nt], ah[mt], bh[nt]);
                mma16816(acc[mt][nt], al[mt], bh[nt]);
            }
    }
}

template <int MODE, int BM, int BN, int NT>
__global__ __launch_bounds__(NT, 1)
void hmma_gemm_kernel(const float* __restrict__ bb, float* __restrict__ out) {
    constexpr int NCHUNK = (MODE == 1) ? 132 : 128;
    constexpr int MT = BM / 32;        // main: 4, h: 2 (two wm slabs)
    extern __shared__ char smem[];
    uint32_t sbase = smem_u32(smem);

    int tid = threadIdx.x;
    int wid = tid >> 5, lane = tid & 31;
    int wm = wid & 1;
    int wn64 = wid >> 1;

    int m0, n0;
    if (MODE == 1) {
        int bid = blockIdx.x;
        int sg = bid >> 6, idx = bid & 63;      // 8x8 supergroups
        int mg = sg & 7, ng = sg >> 3;
        m0 = (mg * 8 + (idx & 7)) * 128;
        n0 = (ng * 8 + (idx >> 3)) * 256;
    } else {
        m0 = blockIdx.x * BM; n0 = 0;
    }

    uint32_t aLane = (uint32_t)((lane & 15) * RS + (lane >> 4) * 16);
    uint32_t bLane = (uint32_t)(((lane & 7) + ((lane >> 4) & 1) * 8) * RS + ((lane >> 3) & 1) * 16);

    float acc[MT][8][4];
#pragma unroll
    for (int a = 0; a < MT; a++)
#pragma unroll
        for (int b = 0; b < 8; b++)
#pragma unroll
            for (int c = 0; c < 4; c++) acc[a][b][c] = 0.f;

    issue_chunk<MODE, BM, BN, NT>(sbase, 0, 0, m0, n0, tid); CP_COMMIT();
    issue_chunk<MODE, BM, BN, NT>(sbase, 1, 1, m0, n0, tid); CP_COMMIT();
    issue_chunk<MODE, BM, BN, NT>(sbase, 2, 2, m0, n0, tid); CP_COMMIT();

#pragma unroll 1
    for (int i = 0; i < NCHUNK; i++) {
        CP_WAIT2();
        __syncthreads();
        if (i + 3 < NCHUNK)
            issue_chunk<MODE, BM, BN, NT>(sbase, (i + 3) & (NSTG - 1), i + 3, m0, n0, tid);
        CP_COMMIT();
        compute_stage<BM, BN, MT>(sbase, i & (NSTG - 1), wm, wn64, aLane, bLane, acc);
    }

    // ---- epilogue ----
    int g = lane >> 2, t = lane & 3;
    if (MODE == 1) {
#pragma unroll
        for (int mt = 0; mt < MT; mt++) {
            int r0 = m0 + wm * (MT * 16) + mt * 16 + g;
#pragma unroll
            for (int nt = 0; nt < 8; nt++) {
                int cc = n0 + wn64 * 64 + nt * 8 + t * 2;
                float2 bv = *(const float2*)(bb + cc);
                float2 v0 = make_float2(acc[mt][nt][0] + bv.x, acc[mt][nt][1] + bv.y);
                float2 v1 = make_float2(acc[mt][nt][2] + bv.x, acc[mt][nt][3] + bv.y);
                *(float2*)(out + (size_t)r0 * ODIM + cc) = v0;
                *(float2*)(out + (size_t)(r0 + 8) * ODIM + cc) = v1;
            }
        }
    } else {
#pragma unroll
        for (int mt = 0; mt < MT; mt++) {
            int r0 = m0 + wm * (MT * 16) + mt * 16 + g;
            int r1 = r0 + 8;
#pragma unroll
            for (int nt = 0; nt < 8; nt++) {
                int cc = wn64 * 64 + nt * 8 + t * 2;
                int e = (wn64 * 64 + nt * 8) >> 4;
                float w0 = g_w[r0 * NEXP + e];
                float w1 = g_w[r1 * NEXP + e];
                float v00 = acc[mt][nt][0] * w0, v01 = acc[mt][nt][1] * w0;
                float v10 = acc[mt][nt][2] * w1, v11 = acc[mt][nt][3] * w1;
                __half h0, l0, h1, l1;
                split1(v00, h0, l0); split1(v01, h1, l1);
                *(__half2*)(g_ghi + (size_t)r0 * KLORA + cc) = __half2(h0, h1);
                *(__half2*)(g_glo + (size_t)r0 * KLORA + cc) = __half2(l0, l1);
                split1(v10, h0, l0); split1(v11, h1, l1);
                *(__half2*)(g_ghi + (size_t)r1 * KLORA + cc) = __half2(h0, h1);
                *(__half2*)(g_glo + (size_t)r1 * KLORA + cc) = __half2(l0, l1);
            }
        }
    }
}

// ---------------------------------------------------------------------------
extern "C" void kernel_launch(void* const* d_in, const int* in_sizes, int n_in,
                              void* d_out, int out_size) {
    const float* x  = (const float*)d_in[0];
    const float* Wb = (const float*)d_in[1];
    const float* bb = (const float*)d_in[2];
    const float* Wg = (const float*)d_in[3];
    const float* Wt = (const float*)d_in[4];
    const float* bt = (const float*)d_in[5];
    const float* Aw = (const float*)d_in[6];
    const float* Bw = (const float*)d_in[7];
    float* out = (float*)d_out;

    constexpr int SMEM_MAIN = NSTG * (2 * 128 * RS + 256 * RS);  // 163840
    constexpr int SMEM_H    = NSTG * (2 * 64 * RS + 128 * RS);   // 81920
    cudaFuncSetAttribute(hmma_gemm_kernel<1, 128, 256, 256>, cudaFuncAttributeMaxDynamicSharedMemorySize, SMEM_MAIN);
    cudaFuncSetAttribute(hmma_gemm_kernel<0, 64, 128, 128>, cudaFuncAttributeMaxDynamicSharedMemorySize, SMEM_H);

    { int n4 = NTOK * DIM / 4;  split_kernel<<<(n4 + 255) / 256, 256>>>(x, 0, n4); }
    { int n4 = ODIM * DIM / 4;  split_kernel<<<(n4 + 255) / 256, 256>>>(Wb, 1, n4); }
    { int n4 = KLORA * DIM / 4; split_kernel<<<(n4 + 255) / 256, 256>>>(Aw, 2, n4); }
    build_bc_kernel<<<(ODIM * KLORA + 255) / 256, 256>>>(Bw);
    gate_kernel<<<NTOK / GT, 256>>>(x, Wg, Wt, bt);

    hmma_gemm_kernel<0, 64, 128, 128><<<NTOK / 64, 128, SMEM_H>>>(nullptr, nullptr);
    hmma_gemm_kernel<1, 128, 256, 256><<<(NTOK / 128) * (ODIM / 256), 256, SMEM_MAIN>>>(bb, out);
}

// round 8
// speedup vs baseline: 1.9937x; 1.0022x over previous
#include <cuda_runtime.h>
#include <cuda_fp16.h>
#include <cstdint>

#define NTOK 8192
#define DIM 4096
#define ODIM 4096
#define NEXP 8
#define RNK 16
#define KLORA 128
#define SCALING_F 2.0f
#define MAXTHR 0.125f

// ---------------- device scratch --------------------------------------------
__device__ float g_w[NTOK * NEXP];
__device__ __half g_xhi[(size_t)NTOK * DIM];
__device__ __half g_xlo[(size_t)NTOK * DIM];
__device__ __half g_Wh[(size_t)ODIM * DIM];
__device__ __half g_Ah[KLORA * DIM];
__device__ __half g_Bc[ODIM * KLORA];
__device__ __half g_ghi[NTOK * KLORA];
__device__ __half g_glo[NTOK * KLORA];

// ---------------- PTX helpers -----------------------------------------------
__device__ __forceinline__ uint32_t smem_u32(const void* p) {
    uint32_t a;
    asm("{ .reg .u64 t; cvta.to.shared.u64 t, %1; cvt.u32.u64 %0, t; }" : "=r"(a) : "l"(p));
    return a;
}
__device__ __forceinline__ void cp16(uint32_t dst, const void* src) {
    asm volatile("cp.async.cg.shared.global [%0], [%1], 16;" :: "r"(dst), "l"(src));
}
#define CP_COMMIT() asm volatile("cp.async.commit_group;" ::: "memory")
#define CP_WAIT2()  asm volatile("cp.async.wait_group 2;" ::: "memory")

__device__ __forceinline__ void ldsm4(uint32_t& r0, uint32_t& r1, uint32_t& r2, uint32_t& r3,
                                      uint32_t addr) {
    asm volatile("ldmatrix.sync.aligned.m8n8.x4.shared.b16 {%0,%1,%2,%3}, [%4];"
                 : "=r"(r0), "=r"(r1), "=r"(r2), "=r"(r3) : "r"(addr));
}
__device__ __forceinline__ void mma16816(float* d, const uint32_t* a, const uint32_t* b) {
    asm volatile("mma.sync.aligned.m16n8k16.row.col.f32.f16.f16.f32 "
                 "{%0,%1,%2,%3}, {%4,%5,%6,%7}, {%8,%9}, {%0,%1,%2,%3};"
                 : "+f"(d[0]), "+f"(d[1]), "+f"(d[2]), "+f"(d[3])
                 : "r"(a[0]), "r"(a[1]), "r"(a[2]), "r"(a[3]), "r"(b[0]), "r"(b[1]));
}

__device__ __forceinline__ void split1(float v, __half& h, __half& l) {
    h = __float2half_rn(v);
    l = __float2half_rn(v - __half2float(h));
}

// ---------------- fused prep kernel ------------------------------------------
// Block ranges: [0, GATE) gate | [GATE, GATE+XS) x-split | then W-split,
// A-split, Bc-build. One launch covers all preprocessing.
#define GT 4
#define NB_GATE (NTOK / GT)                         // 2048
#define NB_XS   (NTOK * DIM / 4 / 256)              // 32768
#define NB_WS   (ODIM * DIM / 4 / 256)              // 16384
#define NB_AS   (KLORA * DIM / 4 / 256)             // 512
#define NB_BC   (ODIM * KLORA / 4 / 256)            // 512
#define NB_TOTAL (NB_GATE + NB_XS + NB_WS + NB_AS + NB_BC)

__global__ __launch_bounds__(256)
void prep_kernel(const float* __restrict__ x,
                 const float* __restrict__ Wb,
                 const float* __restrict__ Wg,
                 const float* __restrict__ Wt,
                 const float* __restrict__ bt,
                 const float* __restrict__ Aw,
                 const float* __restrict__ Bw) {
    int bid = blockIdx.x;
    int tid = threadIdx.x;

    if (bid < NB_GATE) {
        // ---- gate part ----
        int n0 = bid * GT;
        float acc[GT][9];
#pragma unroll
        for (int t = 0; t < GT; t++)
#pragma unroll
            for (int i = 0; i < 9; i++) acc[t][i] = 0.f;
        for (int d = tid; d < DIM; d += 256) {
            float wv[9];
#pragma unroll
            for (int e = 0; e < NEXP; e++) wv[e] = Wg[e * DIM + d];
            wv[8] = Wt[d];
#pragma unroll
            for (int t = 0; t < GT; t++) {
                float xv = x[(size_t)(n0 + t) * DIM + d];
#pragma unroll
                for (int i = 0; i < 9; i++) acc[t][i] = fmaf(xv, wv[i], acc[t][i]);
            }
        }
#pragma unroll
        for (int t = 0; t < GT; t++)
#pragma unroll
            for (int i = 0; i < 9; i++)
#pragma unroll
                for (int off = 16; off; off >>= 1)
                    acc[t][i] += __shfl_down_sync(0xffffffffu, acc[t][i], off);
        __shared__ float sred[8][GT][9];
        int warp = tid >> 5, lane = tid & 31;
        if (lane == 0)
#pragma unroll
            for (int t = 0; t < GT; t++)
#pragma unroll
                for (int i = 0; i < 9; i++) sred[warp][t][i] = acc[t][i];
        __syncthreads();
        if (tid < GT) {
            int t = tid;
            float v[9];
#pragma unroll
            for (int i = 0; i < 9; i++) {
                float s = 0.f;
#pragma unroll
                for (int w2 = 0; w2 < 8; w2++) s += sred[w2][t][i];
                v[i] = s;
            }
            float mx = v[0];
#pragma unroll
            for (int e = 1; e < NEXP; e++) mx = fmaxf(mx, v[e]);
            float se = 0.f, gate[NEXP];
#pragma unroll
            for (int e = 0; e < NEXP; e++) { gate[e] = expf(v[e] - mx); se += gate[e]; }
            float inv = 1.f / se;
            float thr = MAXTHR / (1.f + expf(-(v[8] + bt[0])));
            float w[NEXP]; float ws = 0.f;
#pragma unroll
            for (int e = 0; e < NEXP; e++) {
                float a = gate[e] * inv - thr;
                w[e] = (a >= 0.f) ? a : 0.f;
                ws += w[e];
            }
            if (ws == 0.f) ws = 1.f;
            float sc = SCALING_F / ws;
#pragma unroll
            for (int e = 0; e < NEXP; e++) g_w[(n0 + t) * NEXP + e] = w[e] * sc;
        }
        return;
    }
    bid -= NB_GATE;

    if (bid < NB_XS) {
        // ---- x split (hi/lo fp16) ----
        int i = bid * 256 + tid;
        float4 v = ((const float4*)x)[i];
        __half h0, h1, h2, h3, l0, l1, l2, l3;
        split1(v.x, h0, l0); split1(v.y, h1, l1); split1(v.z, h2, l2); split1(v.w, h3, l3);
        ((__half2*)g_xhi)[2 * i]     = __half2(h0, h1);
        ((__half2*)g_xhi)[2 * i + 1] = __half2(h2, h3);
        ((__half2*)g_xlo)[2 * i]     = __half2(l0, l1);
        ((__half2*)g_xlo)[2 * i + 1] = __half2(l2, l3);
        return;
    }
    bid -= NB_XS;

    if (bid < NB_WS) {
        // ---- W -> fp16 ----
        int i = bid * 256 + tid;
        float4 v = ((const float4*)Wb)[i];
        ((__half2*)g_Wh)[2 * i]     = __half2(__float2half_rn(v.x), __float2half_rn(v.y));
        ((__half2*)g_Wh)[2 * i + 1] = __half2(__float2half_rn(v.z), __float2half_rn(v.w));
        return;
    }
    bid -= NB_WS;

    if (bid < NB_AS) {
        // ---- A_w -> fp16 ----
        int i = bid * 256 + tid;
        float4 v = ((const float4*)Aw)[i];
        ((__half2*)g_Ah)[2 * i]     = __half2(__float2half_rn(v.x), __float2half_rn(v.y));
        ((__half2*)g_Ah)[2 * i + 1] = __half2(__float2half_rn(v.z), __float2half_rn(v.w));
        return;
    }
    bid -= NB_AS;

    {
        // ---- B_w reorder -> [O,128] fp16 ----
        int i = bid * 256 + tid;          // covers ODIM*KLORA/4
        int idx = i * 4;
        int o = idx >> 7, k = idx & 127;
        int e = k >> 4, r = k & 15;       // 4 consecutive k share e; r..r+3 contiguous
        const float* src = Bw + ((size_t)e * ODIM + o) * RNK + r;
        float4 v = *(const float4*)src;
        ((__half2*)g_Bc)[2 * i]     = __half2(__float2half_rn(v.x), __float2half_rn(v.y));
        ((__half2*)g_Bc)[2 * i + 1] = __half2(__float2half_rn(v.z), __float2half_rn(v.w));
        return;
    }
}

// ---------------- HMMA GEMM --------------------------------------------------
// smem rows of 32 fp16 (64B), row stride 80B => conflict-free ldmatrix
#define RS 80
#define NSTG 4

template <int MODE, int BM, int BN, int NT>
__device__ __forceinline__ void issue_chunk(uint32_t sbase, int stage, int chunk,
                                            int m0, int n0, int tid) {
    constexpr int AB = BM * RS;
    constexpr int BB = BN * RS;
    constexpr int STAGE_B = 2 * AB + BB;
    const __half *Ahi, *Alo, *Bh;
    int sA, sB, rA, rB, kcol;
    if (MODE == 1 && chunk >= 128) {
        kcol = (chunk - 128) * 32;
        Ahi = g_ghi; Alo = g_glo; sA = KLORA; rA = m0;
        Bh = g_Bc; sB = KLORA; rB = n0;
    } else if (MODE == 1) {
        kcol = chunk * 32;
        Ahi = g_xhi; Alo = g_xlo; sA = DIM; rA = m0;
        Bh = g_Wh; sB = DIM; rB = n0;
    } else {
        kcol = chunk * 32;
        Ahi = g_xhi; Alo = g_xlo; sA = DIM; rA = m0;
        Bh = g_Ah; sB = DIM; rB = 0;
    }
    uint32_t base = sbase + stage * STAGE_B;
#pragma unroll
    for (int c = tid; c < BM * 4; c += NT) {
        int row = c >> 2, k16 = c & 3;
        uint32_t dof = row * RS + k16 * 16;
        size_t off = (size_t)(rA + row) * sA + kcol + k16 * 8;
        cp16(base + dof, Ahi + off);
        cp16(base + AB + dof, Alo + off);
    }
#pragma unroll
    for (int c = tid; c < BN * 4; c += NT) {
        int row = c >> 2, k16 = c & 3;
        uint32_t dof = row * RS + k16 * 16;
        cp16(base + 2 * AB + dof, Bh + (size_t)(rB + row) * sB + kcol + k16 * 8);
    }
}

template <int BM, int BN, int MT>
__device__ __forceinline__ void compute_stage(uint32_t sbase, int stage, int wm, int wn64,
                                              uint32_t aLane, uint32_t bLane,
                                              float acc[MT][8][4]) {
    constexpr int AB = BM * RS;
    constexpr int BB = BN * RS;
    constexpr int STAGE_B = 2 * AB + BB;
    uint32_t base = sbase + stage * STAGE_B;
    uint32_t aHiB = base + wm * (MT * 16) * RS + aLane;
    uint32_t bB = base + 2 * AB + wn64 * 64 * RS + bLane;
#pragma unroll
    for (int s = 0; s < 2; s++) {
        uint32_t ah[MT][4], al[MT][4], bh[8][2];
#pragma unroll
        for (int mt = 0; mt < MT; mt++) {
            ldsm4(ah[mt][0], ah[mt][1], ah[mt][2], ah[mt][3], aHiB + mt * 16 * RS + s * 32);
            ldsm4(al[mt][0], al[mt][1], al[mt][2], al[mt][3],
                  aHiB + AB + mt * 16 * RS + s * 32);
        }
#pragma unroll
        for (int p = 0; p < 4; p++)
            ldsm4(bh[2 * p][0], bh[2 * p][1], bh[2 * p + 1][0], bh[2 * p + 1][1],
                  bB + p * 16 * RS + s * 32);
#pragma unroll
        for (int mt = 0; mt < MT; mt++)
#pragma unroll
            for (int nt = 0; nt < 8; nt++) {
                mma16816(acc[mt][nt], ah[mt], bh[nt]);
                mma16816(acc[mt][nt], al[mt], bh[nt]);
            }
    }
}

template <int MODE, int BM, int BN, int NT>
__global__ __launch_bounds__(NT, 1)
void hmma_gemm_kernel(const float* __restrict__ bb, float* __restrict__ out) {
    constexpr int NCHUNK = (MODE == 1) ? 132 : 128;
    constexpr int MT = BM / 32;
    extern __shared__ char smem[];
    uint32_t sbase = smem_u32(smem);

    int tid = threadIdx.x;
    int wid = tid >> 5, lane = tid & 31;
    int wm = wid & 1;
    int wn64 = wid >> 1;

    int m0, n0;
    if (MODE == 1) {
        int bid = blockIdx.x;
        int sg = bid >> 6, idx = bid & 63;      // 8x8 supergroups
        int mg = sg & 7, ng = sg >> 3;
        m0 = (mg * 8 + (idx & 7)) * 128;
        n0 = (ng * 8 + (idx >> 3)) * 256;
    } else {
        m0 = blockIdx.x * BM; n0 = 0;
    }

    uint32_t aLane = (uint32_t)((lane & 15) * RS + (lane >> 4) * 16);
    uint32_t bLane = (uint32_t)(((lane & 7) + ((lane >> 4) & 1) * 8) * RS + ((lane >> 3) & 1) * 16);

    float acc[MT][8][4];
#pragma unroll
    for (int a = 0; a < MT; a++)
#pragma unroll
        for (int b = 0; b < 8; b++)
#pragma unroll
            for (int c = 0; c < 4; c++) acc[a][b][c] = 0.f;

    issue_chunk<MODE, BM, BN, NT>(sbase, 0, 0, m0, n0, tid); CP_COMMIT();
    issue_chunk<MODE, BM, BN, NT>(sbase, 1, 1, m0, n0, tid); CP_COMMIT();
    issue_chunk<MODE, BM, BN, NT>(sbase, 2, 2, m0, n0, tid); CP_COMMIT();

#pragma unroll 1
    for (int i = 0; i < NCHUNK; i++) {
        CP_WAIT2();
        __syncthreads();
        if (i + 3 < NCHUNK)
            issue_chunk<MODE, BM, BN, NT>(sbase, (i + 3) & (NSTG - 1), i + 3, m0, n0, tid);
        CP_COMMIT();
        compute_stage<BM, BN, MT>(sbase, i & (NSTG - 1), wm, wn64, aLane, bLane, acc);
    }

    // ---- epilogue ----
    int g = lane >> 2, t = lane & 3;
    if (MODE == 1) {
#pragma unroll
        for (int mt = 0; mt < MT; mt++) {
            int r0 = m0 + wm * (MT * 16) + mt * 16 + g;
#pragma unroll
            for (int nt = 0; nt < 8; nt++) {
                int cc = n0 + wn64 * 64 + nt * 8 + t * 2;
                float2 bv = *(const float2*)(bb + cc);
                float2 v0 = make_float2(acc[mt][nt][0] + bv.x, acc[mt][nt][1] + bv.y);
                float2 v1 = make_float2(acc[mt][nt][2] + bv.x, acc[mt][nt][3] + bv.y);
                *(float2*)(out + (size_t)r0 * ODIM + cc) = v0;
                *(float2*)(out + (size_t)(r0 + 8) * ODIM + cc) = v1;
            }
        }
    } else {
#pragma unroll
        for (int mt = 0; mt < MT; mt++) {
            int r0 = m0 + wm * (MT * 16) + mt * 16 + g;
            int r1 = r0 + 8;
#pragma unroll
            for (int nt = 0; nt < 8; nt++) {
                int cc = wn64 * 64 + nt * 8 + t * 2;
                int e = (wn64 * 64 + nt * 8) >> 4;
                float w0 = g_w[r0 * NEXP + e];
                float w1 = g_w[r1 * NEXP + e];
                float v00 = acc[mt][nt][0] * w0, v01 = acc[mt][nt][1] * w0;
                float v10 = acc[mt][nt][2] * w1, v11 = acc[mt][nt][3] * w1;
                __half h0, l0, h1, l1;
                split1(v00, h0, l0); split1(v01, h1, l1);
                *(__half2*)(g_ghi + (size_t)r0 * KLORA + cc) = __half2(h0, h1);
                *(__half2*)(g_glo + (size_t)r0 * KLORA + cc) = __half2(l0, l1);
                split1(v10, h0, l0); split1(v11, h1, l1);
                *(__half2*)(g_ghi + (size_t)r1 * KLORA + cc) = __half2(h0, h1);
                *(__half2*)(g_glo + (size_t)r1 * KLORA + cc) = __half2(l0, l1);
            }
        }
    }
}

// ---------------------------------------------------------------------------
extern "C" void kernel_launch(void* const* d_in, const int* in_sizes, int n_in,
                              void* d_out, int out_size) {
    const float* x  = (const float*)d_in[0];
    const float* Wb = (const float*)d_in[1];
    const float* bb = (const float*)d_in[2];
    const float* Wg = (const float*)d_in[3];
    const float* Wt = (const float*)d_in[4];
    const float* bt = (const float*)d_in[5];
    const float* Aw = (const float*)d_in[6];
    const float* Bw = (const float*)d_in[7];
    float* out = (float*)d_out;

    constexpr int SMEM_MAIN = NSTG * (2 * 128 * RS + 256 * RS);  // 163840
    constexpr int SMEM_H    = NSTG * (2 * 64 * RS + 128 * RS);   // 81920
    cudaFuncSetAttribute(hmma_gemm_kernel<1, 128, 256, 256>, cudaFuncAttributeMaxDynamicSharedMemorySize, SMEM_MAIN);
    cudaFuncSetAttribute(hmma_gemm_kernel<0, 64, 128, 128>, cudaFuncAttributeMaxDynamicSharedMemorySize, SMEM_H);

    prep_kernel<<<NB_TOTAL, 256>>>(x, Wb, Wg, Wt, bt, Aw, Bw);
    hmma_gemm_kernel<0, 64, 128, 128><<<NTOK / 64, 128, SMEM_H>>>(nullptr, nullptr);
    hmma_gemm_kernel<1, 128, 256, 256><<<(NTOK / 128) * (ODIM / 256), 256, SMEM_MAIN>>>(bb, out);
}

// round 9
// speedup vs baseline: 2.0811x; 1.0438x over previous
#include <cuda_runtime.h>
#include <cuda_fp16.h>
#include <cstdint>

#define NTOK 8192
#define DIM 4096
#define ODIM 4096
#define NEXP 8
#define RNK 16
#define KLORA 128
#define SCALING_F 2.0f
#define MAXTHR 0.125f

// ---------------- device scratch --------------------------------------------
__device__ float g_w[NTOK * NEXP];
__device__ __half g_xhi[(size_t)NTOK * DIM];
__device__ __half g_xlo[(size_t)NTOK * DIM];
__device__ __half g_Wh[(size_t)ODIM * DIM];
__device__ __half g_Ah[KLORA * DIM];
__device__ __half g_Bc[ODIM * KLORA];
__device__ __half g_ghi[NTOK * KLORA];
__device__ __half g_glo[NTOK * KLORA];

// ---------------- PTX helpers -----------------------------------------------
__device__ __forceinline__ uint32_t smem_u32(const void* p) {
    uint32_t a;
    asm("{ .reg .u64 t; cvta.to.shared.u64 t, %1; cvt.u32.u64 %0, t; }" : "=r"(a) : "l"(p));
    return a;
}
__device__ __forceinline__ void cp16(uint32_t dst, const void* src) {
    asm volatile("cp.async.cg.shared.global [%0], [%1], 16;" :: "r"(dst), "l"(src));
}
#define CP_COMMIT() asm volatile("cp.async.commit_group;" ::: "memory")
#define CP_WAIT1()  asm volatile("cp.async.wait_group 1;" ::: "memory")

__device__ __forceinline__ void ldsm4(uint32_t& r0, uint32_t& r1, uint32_t& r2, uint32_t& r3,
                                      uint32_t addr) {
    asm volatile("ldmatrix.sync.aligned.m8n8.x4.shared.b16 {%0,%1,%2,%3}, [%4];"
                 : "=r"(r0), "=r"(r1), "=r"(r2), "=r"(r3) : "r"(addr));
}
__device__ __forceinline__ void mma16816(float* d, const uint32_t* a, const uint32_t* b) {
    asm volatile("mma.sync.aligned.m16n8k16.row.col.f32.f16.f16.f32 "
                 "{%0,%1,%2,%3}, {%4,%5,%6,%7}, {%8,%9}, {%0,%1,%2,%3};"
                 : "+f"(d[0]), "+f"(d[1]), "+f"(d[2]), "+f"(d[3])
                 : "r"(a[0]), "r"(a[1]), "r"(a[2]), "r"(a[3]), "r"(b[0]), "r"(b[1]));
}

__device__ __forceinline__ void split1(float v, __half& h, __half& l) {
    h = __float2half_rn(v);
    l = __float2half_rn(v - __half2float(h));
}

// ---------------- fused prep kernel ------------------------------------------
// Ranges: [0, XG) x-split+gate (4 rows/block) | W-split | A-split | Bc-build.
#define NB_XG (NTOK / 4)                            // 2048
#define NB_WS (ODIM * DIM / 4 / 256)                // 16384
#define NB_AS (KLORA * DIM / 4 / 256)               // 512
#define NB_BC (ODIM * KLORA / 4 / 256)              // 512
#define NB_TOTAL (NB_XG + NB_WS + NB_AS + NB_BC)

__global__ __launch_bounds__(256)
void prep_kernel(const float* __restrict__ x,
                 const float* __restrict__ Wb,
                 const float* __restrict__ Wg,
                 const float* __restrict__ Wt,
                 const float* __restrict__ bt,
                 const float* __restrict__ Aw,
                 const float* __restrict__ Bw) {
    int bid = blockIdx.x;
    int tid = threadIdx.x;

    if (bid < NB_XG) {
        // ---- x split + gate: 4 rows, 64 threads per row ----
        int n0 = bid * 4;
        int r = tid >> 6;                 // row within group
        int c = tid & 63;                 // float4 lane within row
        int row = n0 + r;
        const float4* xrow = (const float4*)x + (size_t)row * (DIM / 4);
        float acc[9];
#pragma unroll
        for (int i = 0; i < 9; i++) acc[i] = 0.f;

#pragma unroll 4
        for (int j = 0; j < 16; j++) {
            int idx = c + j * 64;         // float4 index in row
            float4 v = xrow[idx];
            // gate dots
#pragma unroll
            for (int e = 0; e < NEXP; e++) {
                float4 wv = ((const float4*)Wg)[e * (DIM / 4) + idx];
                acc[e] = fmaf(v.x, wv.x, fmaf(v.y, wv.y, fmaf(v.z, wv.z, fmaf(v.w, wv.w, acc[e]))));
            }
            float4 wt = ((const float4*)Wt)[idx];
            acc[8] = fmaf(v.x, wt.x, fmaf(v.y, wt.y, fmaf(v.z, wt.z, fmaf(v.w, wt.w, acc[8]))));
            // split
            __half h0, h1, h2, h3, l0, l1, l2, l3;
            split1(v.x, h0, l0); split1(v.y, h1, l1); split1(v.z, h2, l2); split1(v.w, h3, l3);
            size_t o = (size_t)row * (DIM / 4) + idx;
            ((__half2*)g_xhi)[2 * o]     = __half2(h0, h1);
            ((__half2*)g_xhi)[2 * o + 1] = __half2(h2, h3);
            ((__half2*)g_xlo)[2 * o]     = __half2(l0, l1);
            ((__half2*)g_xlo)[2 * o + 1] = __half2(l2, l3);
        }
        // reduce: warp shuffle, then combine 2 warps per row
#pragma unroll
        for (int i = 0; i < 9; i++)
#pragma unroll
            for (int off = 16; off; off >>= 1)
                acc[i] += __shfl_down_sync(0xffffffffu, acc[i], off);
        __shared__ float sred[8][9];
        int warp = tid >> 5, lane = tid & 31;
        if (lane == 0)
#pragma unroll
            for (int i = 0; i < 9; i++) sred[warp][i] = acc[i];
        __syncthreads();
        if (tid < 4) {
            int t = tid;
            float v[9];
#pragma unroll
            for (int i = 0; i < 9; i++) v[i] = sred[2 * t][i] + sred[2 * t + 1][i];
            float mx = v[0];
#pragma unroll
            for (int e = 1; e < NEXP; e++) mx = fmaxf(mx, v[e]);
            float se = 0.f, gate[NEXP];
#pragma unroll
            for (int e = 0; e < NEXP; e++) { gate[e] = expf(v[e] - mx); se += gate[e]; }
            float inv = 1.f / se;
            float thr = MAXTHR / (1.f + expf(-(v[8] + bt[0])));
            float w[NEXP]; float ws = 0.f;
#pragma unroll
            for (int e = 0; e < NEXP; e++) {
                float a = gate[e] * inv - thr;
                w[e] = (a >= 0.f) ? a : 0.f;
                ws += w[e];
            }
            if (ws == 0.f) ws = 1.f;
            float sc = SCALING_F / ws;
#pragma unroll
            for (int e = 0; e < NEXP; e++) g_w[(n0 + t) * NEXP + e] = w[e] * sc;
        }
        return;
    }
    bid -= NB_XG;

    if (bid < NB_WS) {
        int i = bid * 256 + tid;
        float4 v = ((const float4*)Wb)[i];
        ((__half2*)g_Wh)[2 * i]     = __half2(__float2half_rn(v.x), __float2half_rn(v.y));
        ((__half2*)g_Wh)[2 * i + 1] = __half2(__float2half_rn(v.z), __float2half_rn(v.w));
        return;
    }
    bid -= NB_WS;

    if (bid < NB_AS) {
        int i = bid * 256 + tid;
        float4 v = ((const float4*)Aw)[i];
        ((__half2*)g_Ah)[2 * i]     = __half2(__float2half_rn(v.x), __float2half_rn(v.y));
        ((__half2*)g_Ah)[2 * i + 1] = __half2(__float2half_rn(v.z), __float2half_rn(v.w));
        return;
    }
    bid -= NB_AS;

    {
        int i = bid * 256 + tid;
        int idx = i * 4;
        int o = idx >> 7, k = idx & 127;
        int e = k >> 4, r = k & 15;
        const float* src = Bw + ((size_t)e * ODIM + o) * RNK + r;
        float4 v = *(const float4*)src;
        ((__half2*)g_Bc)[2 * i]     = __half2(__float2half_rn(v.x), __float2half_rn(v.y));
        ((__half2*)g_Bc)[2 * i + 1] = __half2(__float2half_rn(v.z), __float2half_rn(v.w));
        return;
    }
}

// ---------------- HMMA GEMM --------------------------------------------------
// smem rows of 32 fp16 (64B), row stride 80B => conflict-free ldmatrix
#define RS 80
#define NSTG 3

// MODE 1: main, BM=128, BN=128, NT=128, 2 CTAs/SM. MODE 0: h-gemm, BM=64, BN=128, NT=128.
template <int MODE, int BM, int BN, int NT>
__device__ __forceinline__ void issue_chunk(uint32_t sbase, int stage, int chunk,
                                            int m0, int n0, int tid) {
    constexpr int AB = BM * RS;
    constexpr int BB = BN * RS;
    constexpr int STAGE_B = 2 * AB + BB;
    const __half *Ahi, *Alo, *Bh;
    int sA, sB, rA, rB, kcol;
    if (MODE == 1 && chunk >= 128) {
        kcol = (chunk - 128) * 32;
        Ahi = g_ghi; Alo = g_glo; sA = KLORA; rA = m0;
        Bh = g_Bc; sB = KLORA; rB = n0;
    } else if (MODE == 1) {
        kcol = chunk * 32;
        Ahi = g_xhi; Alo = g_xlo; sA = DIM; rA = m0;
        Bh = g_Wh; sB = DIM; rB = n0;
    } else {
        kcol = chunk * 32;
        Ahi = g_xhi; Alo = g_xlo; sA = DIM; rA = m0;
        Bh = g_Ah; sB = DIM; rB = 0;
    }
    uint32_t base = sbase + stage * STAGE_B;
#pragma unroll
    for (int c = tid; c < BM * 4; c += NT) {
        int row = c >> 2, k16 = c & 3;
        uint32_t dof = row * RS + k16 * 16;
        size_t off = (size_t)(rA + row) * sA + kcol + k16 * 8;
        cp16(base + dof, Ahi + off);
        cp16(base + AB + dof, Alo + off);
    }
#pragma unroll
    for (int c = tid; c < BN * 4; c += NT) {
        int row = c >> 2, k16 = c & 3;
        uint32_t dof = row * RS + k16 * 16;
        cp16(base + 2 * AB + dof, Bh + (size_t)(rB + row) * sB + kcol + k16 * 8);
    }
}

template <int BM, int BN, int MT>
__device__ __forceinline__ void compute_stage(uint32_t sbase, int stage, int wm, int wn64,
                                              uint32_t aLane, uint32_t bLane,
                                              float acc[MT][8][4]) {
    constexpr int AB = BM * RS;
    constexpr int BB = BN * RS;
    constexpr int STAGE_B = 2 * AB + BB;
    uint32_t base = sbase + stage * STAGE_B;
    uint32_t aHiB = base + wm * (MT * 16) * RS + aLane;
    uint32_t bB = base + 2 * AB + wn64 * 64 * RS + bLane;
#pragma unroll
    for (int s = 0; s < 2; s++) {
        uint32_t ah[MT][4], al[MT][4], bh[8][2];
#pragma unroll
        for (int mt = 0; mt < MT; mt++) {
            ldsm4(ah[mt][0], ah[mt][1], ah[mt][2], ah[mt][3], aHiB + mt * 16 * RS + s * 32);
            ldsm4(al[mt][0], al[mt][1], al[mt][2], al[mt][3],
                  aHiB + AB + mt * 16 * RS + s * 32);
        }
#pragma unroll
        for (int p = 0; p < 4; p++)
            ldsm4(bh[2 * p][0], bh[2 * p][1], bh[2 * p + 1][0], bh[2 * p + 1][1],
                  bB + p * 16 * RS + s * 32);
#pragma unroll
        for (int mt = 0; mt < MT; mt++)
#pragma unroll
            for (int nt = 0; nt < 8; nt++) {
                mma16816(acc[mt][nt], ah[mt], bh[nt]);
                mma16816(acc[mt][nt], al[mt], bh[nt]);
            }
    }
}

template <int MODE, int BM, int BN, int NT>
__global__ __launch_bounds__(NT, 2)
void hmma_gemm_kernel(const float* __restrict__ bb, float* __restrict__ out) {
    constexpr int NCHUNK = (MODE == 1) ? 132 : 128;
    constexpr int MT = BM / 32;     // main: 4, h: 2
    extern __shared__ char smem[];
    uint32_t sbase = smem_u32(smem);

    int tid = threadIdx.x;
    int wid = tid >> 5, lane = tid & 31;
    int wm = wid & 1;
    int wn64 = wid >> 1;

    int m0, n0;
    if (MODE == 1) {
        int bid = blockIdx.x;
        int sg = bid >> 6, idx = bid & 63;      // 8x8 supergroups of 128x128 tiles
        int mg = sg & 7, ng = sg >> 3;
        m0 = (mg * 8 + (idx & 7)) * 128;
        n0 = (ng * 8 + (idx >> 3)) * 128;
    } else {
        m0 = blockIdx.x * BM; n0 = 0;
    }

    uint32_t aLane = (uint32_t)((lane & 15) * RS + (lane >> 4) * 16);
    uint32_t bLane = (uint32_t)(((lane & 7) + ((lane >> 4) & 1) * 8) * RS + ((lane >> 3) & 1) * 16);

    float acc[MT][8][4];
#pragma unroll
    for (int a = 0; a < MT; a++)
#pragma unroll
        for (int b = 0; b < 8; b++)
#pragma unroll
            for (int c = 0; c < 4; c++) acc[a][b][c] = 0.f;

    issue_chunk<MODE, BM, BN, NT>(sbase, 0, 0, m0, n0, tid); CP_COMMIT();
    issue_chunk<MODE, BM, BN, NT>(sbase, 1, 1, m0, n0, tid); CP_COMMIT();

#pragma unroll 1
    for (int i = 0; i < NCHUNK; i++) {
        CP_WAIT1();
        __syncthreads();
        if (i + 2 < NCHUNK) {
            int st = (i + 2) % NSTG;
            issue_chunk<MODE, BM, BN, NT>(sbase, st, i + 2, m0, n0, tid);
        }
        CP_COMMIT();
        compute_stage<BM, BN, MT>(sbase, i % NSTG, wm, wn64, aLane, bLane, acc);
    }

    // ---- epilogue ----
    int g = lane >> 2, t = lane & 3;
    if (MODE == 1) {
#pragma unroll
        for (int mt = 0; mt < MT; mt++) {
            int r0 = m0 + wm * (MT * 16) + mt * 16 + g;
#pragma unroll
            for (int nt = 0; nt < 8; nt++) {
                int cc = n0 + wn64 * 64 + nt * 8 + t * 2;
                float2 bv = *(const float2*)(bb + cc);
                float2 v0 = make_float2(acc[mt][nt][0] + bv.x, acc[mt][nt][1] + bv.y);
                float2 v1 = make_float2(acc[mt][nt][2] + bv.x, acc[mt][nt][3] + bv.y);
                *(float2*)(out + (size_t)r0 * ODIM + cc) = v0;
                *(float2*)(out + (size_t)(r0 + 8) * ODIM + cc) = v1;
            }
        }
    } else {
#pragma unroll
        for (int mt = 0; mt < MT; mt++) {
            int r0 = m0 + wm * (MT * 16) + mt * 16 + g;
            int r1 = r0 + 8;
#pragma unroll
            for (int nt = 0; nt < 8; nt++) {
                int cc = wn64 * 64 + nt * 8 + t * 2;
                int e = (wn64 * 64 + nt * 8) >> 4;
                float w0 = g_w[r0 * NEXP + e];
                float w1 = g_w[r1 * NEXP + e];
                float v00 = acc[mt][nt][0] * w0, v01 = acc[mt][nt][1] * w0;
                float v10 = acc[mt][nt][2] * w1, v11 = acc[mt][nt][3] * w1;
                __half h0, l0, h1, l1;
                split1(v00, h0, l0); split1(v01, h1, l1);
                *(__half2*)(g_ghi + (size_t)r0 * KLORA + cc) = __half2(h0, h1);
                *(__half2*)(g_glo + (size_t)r0 * KLORA + cc) = __half2(l0, l1);
                split1(v10, h0, l0); split1(v11, h1, l1);
                *(__half2*)(g_ghi + (size_t)r1 * KLORA + cc) = __half2(h0, h1);
                *(__half2*)(g_glo + (size_t)r1 * KLORA + cc) = __half2(l0, l1);
            }
        }
    }
}

// ---------------------------------------------------------------------------
extern "C" void kernel_launch(void* const* d_in, const int* in_sizes, int n_in,
                              void* d_out, int out_size) {
    const float* x  = (const float*)d_in[0];
    const float* Wb = (const float*)d_in[1];
    const float* bb = (const float*)d_in[2];
    const float* Wg = (const float*)d_in[3];
    const float* Wt = (const float*)d_in[4];
    const float* bt = (const float*)d_in[5];
    const float* Aw = (const float*)d_in[6];
    const float* Bw = (const float*)d_in[7];
    float* out = (float*)d_out;

    constexpr int SMEM_MAIN = NSTG * (2 * 128 * RS + 128 * RS);  // 92160 -> 2 CTAs/SM
    constexpr int SMEM_H    = NSTG * (2 * 64 * RS + 128 * RS);   // 61440 -> 2 CTAs/SM
    cudaFuncSetAttribute(hmma_gemm_kernel<1, 128, 128, 128>, cudaFuncAttributeMaxDynamicSharedMemorySize, SMEM_MAIN);
    cudaFuncSetAttribute(hmma_gemm_kernel<0, 64, 128, 128>, cudaFuncAttributeMaxDynamicSharedMemorySize, SMEM_H);

    prep_kernel<<<NB_TOTAL, 256>>>(x, Wb, Wg, Wt, bt, Aw, Bw);
    hmma_gemm_kernel<0, 64, 128, 128><<<NTOK / 64, 128, SMEM_H>>>(nullptr, nullptr);
    hmma_gemm_kernel<1, 128, 128, 128><<<(NTOK / 128) * (ODIM / 128), 128, SMEM_MAIN>>>(bb, out);
}

// round 10
// speedup vs baseline: 4.0986x; 1.9695x over previous
#include <cuda_runtime.h>
#include <cuda_fp16.h>
#include <cstdint>

#define NTOK 8192
#define DIM 4096
#define ODIM 4096
#define NEXP 8
#define RNK 16
#define KLORA 128
#define SCALING_F 2.0f
#define MAXTHR 0.125f

// ---------------- device scratch --------------------------------------------
__device__ float g_w[NTOK * NEXP];
__device__ __half g_xh[(size_t)NTOK * DIM];
__device__ __half g_Wh[(size_t)ODIM * DIM];
__device__ __half g_Ah[KLORA * DIM];
__device__ __half g_Bc[ODIM * KLORA];
__device__ __half g_gh[NTOK * KLORA];

// ---------------- PTX helpers -----------------------------------------------
__device__ __forceinline__ uint32_t smem_u32(const void* p) {
    uint32_t a;
    asm("{ .reg .u64 t; cvta.to.shared.u64 t, %1; cvt.u32.u64 %0, t; }" : "=r"(a) : "l"(p));
    return a;
}
__device__ __forceinline__ void cp16(uint32_t dst, const void* src) {
    asm volatile("cp.async.cg.shared.global [%0], [%1], 16;" :: "r"(dst), "l"(src));
}
#define CP_COMMIT() asm volatile("cp.async.commit_group;" ::: "memory")
#define CP_WAIT1()  asm volatile("cp.async.wait_group 1;" ::: "memory")

__device__ __forceinline__ void ldsm4(uint32_t& r0, uint32_t& r1, uint32_t& r2, uint32_t& r3,
                                      uint32_t addr) {
    asm volatile("ldmatrix.sync.aligned.m8n8.x4.shared.b16 {%0,%1,%2,%3}, [%4];"
                 : "=r"(r0), "=r"(r1), "=r"(r2), "=r"(r3) : "r"(addr));
}
__device__ __forceinline__ void mma16816(float* d, const uint32_t* a, const uint32_t* b) {
    asm volatile("mma.sync.aligned.m16n8k16.row.col.f32.f16.f16.f32 "
                 "{%0,%1,%2,%3}, {%4,%5,%6,%7}, {%8,%9}, {%0,%1,%2,%3};"
                 : "+f"(d[0]), "+f"(d[1]), "+f"(d[2]), "+f"(d[3])
                 : "r"(a[0]), "r"(a[1]), "r"(a[2]), "r"(a[3]), "r"(b[0]), "r"(b[1]));
}

// ---------------- fused prep kernel ------------------------------------------
// Ranges: [0, XG) x-convert+gate (4 rows/block) | W | A | Bc.
#define NB_XG (NTOK / 4)                            // 2048
#define NB_WS (ODIM * DIM / 4 / 256)                // 16384
#define NB_AS (KLORA * DIM / 4 / 256)               // 512
#define NB_BC (ODIM * KLORA / 4 / 256)              // 512
#define NB_TOTAL (NB_XG + NB_WS + NB_AS + NB_BC)

__global__ __launch_bounds__(256)
void prep_kernel(const float* __restrict__ x,
                 const float* __restrict__ Wb,
                 const float* __restrict__ Wg,
                 const float* __restrict__ Wt,
                 const float* __restrict__ bt,
                 const float* __restrict__ Aw,
                 const float* __restrict__ Bw) {
    int bid = blockIdx.x;
    int tid = threadIdx.x;

    if (bid < NB_XG) {
        // ---- x convert + gate: 4 rows, 64 threads per row ----
        int n0 = bid * 4;
        int r = tid >> 6;
        int c = tid & 63;
        int row = n0 + r;
        const float4* xrow = (const float4*)x + (size_t)row * (DIM / 4);
        float acc[9];
#pragma unroll
        for (int i = 0; i < 9; i++) acc[i] = 0.f;

#pragma unroll 4
        for (int j = 0; j < 16; j++) {
            int idx = c + j * 64;
            float4 v = xrow[idx];
#pragma unroll
            for (int e = 0; e < NEXP; e++) {
                float4 wv = ((const float4*)Wg)[e * (DIM / 4) + idx];
                acc[e] = fmaf(v.x, wv.x, fmaf(v.y, wv.y, fmaf(v.z, wv.z, fmaf(v.w, wv.w, acc[e]))));
            }
            float4 wt = ((const float4*)Wt)[idx];
            acc[8] = fmaf(v.x, wt.x, fmaf(v.y, wt.y, fmaf(v.z, wt.z, fmaf(v.w, wt.w, acc[8]))));
            size_t o = (size_t)row * (DIM / 4) + idx;
            ((__half2*)g_xh)[2 * o]     = __half2(__float2half_rn(v.x), __float2half_rn(v.y));
            ((__half2*)g_xh)[2 * o + 1] = __half2(__float2half_rn(v.z), __float2half_rn(v.w));
        }
#pragma unroll
        for (int i = 0; i < 9; i++)
#pragma unroll
            for (int off = 16; off; off >>= 1)
                acc[i] += __shfl_down_sync(0xffffffffu, acc[i], off);
        __shared__ float sred[8][9];
        int warp = tid >> 5, lane = tid & 31;
        if (lane == 0)
#pragma unroll
            for (int i = 0; i < 9; i++) sred[warp][i] = acc[i];
        __syncthreads();
        if (tid < 4) {
            int t = tid;
            float v[9];
#pragma unroll
            for (int i = 0; i < 9; i++) v[i] = sred[2 * t][i] + sred[2 * t + 1][i];
            float mx = v[0];
#pragma unroll
            for (int e = 1; e < NEXP; e++) mx = fmaxf(mx, v[e]);
            float se = 0.f, gate[NEXP];
#pragma unroll
            for (int e = 0; e < NEXP; e++) { gate[e] = expf(v[e] - mx); se += gate[e]; }
            float inv = 1.f / se;
            float thr = MAXTHR / (1.f + expf(-(v[8] + bt[0])));
            float w[NEXP]; float ws = 0.f;
#pragma unroll
            for (int e = 0; e < NEXP; e++) {
                float a = gate[e] * inv - thr;
                w[e] = (a >= 0.f) ? a : 0.f;
                ws += w[e];
            }
            if (ws == 0.f) ws = 1.f;
            float sc = SCALING_F / ws;
#pragma unroll
            for (int e = 0; e < NEXP; e++) g_w[(n0 + t) * NEXP + e] = w[e] * sc;
        }
        return;
    }
    bid -= NB_XG;

    if (bid < NB_WS) {
        int i = bid * 256 + tid;
        float4 v = ((const float4*)Wb)[i];
        ((__half2*)g_Wh)[2 * i]     = __half2(__float2half_rn(v.x), __float2half_rn(v.y));
        ((__half2*)g_Wh)[2 * i + 1] = __half2(__float2half_rn(v.z), __float2half_rn(v.w));
        return;
    }
    bid -= NB_WS;

    if (bid < NB_AS) {
        int i = bid * 256 + tid;
        float4 v = ((const float4*)Aw)[i];
        ((__half2*)g_Ah)[2 * i]     = __half2(__float2half_rn(v.x), __float2half_rn(v.y));
        ((__half2*)g_Ah)[2 * i + 1] = __half2(__float2half_rn(v.z), __float2half_rn(v.w));
        return;
    }
    bid -= NB_AS;

    {
        int i = bid * 256 + tid;
        int idx = i * 4;
        int o = idx >> 7, k = idx & 127;
        int e = k >> 4, r = k & 15;
        const float* src = Bw + ((size_t)e * ODIM + o) * RNK + r;
        float4 v = *(const float4*)src;
        ((__half2*)g_Bc)[2 * i]     = __half2(__float2half_rn(v.x), __float2half_rn(v.y));
        ((__half2*)g_Bc)[2 * i + 1] = __half2(__float2half_rn(v.z), __float2half_rn(v.w));
        return;
    }
}

// ---------------- HMMA GEMM (single fp16 pass) --------------------------------
// smem rows of 32 fp16 (64B), row stride 80B => conflict-free ldmatrix
#define RS 80
#define NSTG 3

// MODE 1: main, BM=128, BN=128, NT=128, 2 CTAs/SM. MODE 0: h-gemm, BM=64.
template <int MODE, int BM, int BN, int NT>
__device__ __forceinline__ void issue_chunk(uint32_t sbase, int stage, int chunk,
                                            int m0, int n0, int tid) {
    constexpr int AB = BM * RS;
    constexpr int BB = BN * RS;
    constexpr int STAGE_B = AB + BB;
    const __half *Ah, *Bh;
    int sA, sB, rA, rB, kcol;
    if (MODE == 1 && chunk >= 128) {
        kcol = (chunk - 128) * 32;
        Ah = g_gh; sA = KLORA; rA = m0;
        Bh = g_Bc; sB = KLORA; rB = n0;
    } else if (MODE == 1) {
        kcol = chunk * 32;
        Ah = g_xh; sA = DIM; rA = m0;
        Bh = g_Wh; sB = DIM; rB = n0;
    } else {
        kcol = chunk * 32;
        Ah = g_xh; sA = DIM; rA = m0;
        Bh = g_Ah; sB = DIM; rB = 0;
    }
    uint32_t base = sbase + stage * STAGE_B;
#pragma unroll
    for (int c = tid; c < BM * 4; c += NT) {
        int row = c >> 2, k16 = c & 3;
        uint32_t dof = row * RS + k16 * 16;
        cp16(base + dof, Ah + (size_t)(rA + row) * sA + kcol + k16 * 8);
    }
#pragma unroll
    for (int c = tid; c < BN * 4; c += NT) {
        int row = c >> 2, k16 = c & 3;
        uint32_t dof = row * RS + k16 * 16;
        cp16(base + AB + dof, Bh + (size_t)(rB + row) * sB + kcol + k16 * 8);
    }
}

template <int BM, int BN, int MT>
__device__ __forceinline__ void compute_stage(uint32_t sbase, int stage, int wm, int wn64,
                                              uint32_t aLane, uint32_t bLane,
                                              float acc[MT][8][4]) {
    constexpr int AB = BM * RS;
    constexpr int BB = BN * RS;
    constexpr int STAGE_B = AB + BB;
    uint32_t base = sbase + stage * STAGE_B;
    uint32_t aB = base + wm * (MT * 16) * RS + aLane;
    uint32_t bB = base + AB + wn64 * 64 * RS + bLane;
#pragma unroll
    for (int s = 0; s < 2; s++) {
        uint32_t ah[MT][4], bh[8][2];
#pragma unroll
        for (int mt = 0; mt < MT; mt++)
            ldsm4(ah[mt][0], ah[mt][1], ah[mt][2], ah[mt][3], aB + mt * 16 * RS + s * 32);
#pragma unroll
        for (int p = 0; p < 4; p++)
            ldsm4(bh[2 * p][0], bh[2 * p][1], bh[2 * p + 1][0], bh[2 * p + 1][1],
                  bB + p * 16 * RS + s * 32);
#pragma unroll
        for (int mt = 0; mt < MT; mt++)
#pragma unroll
            for (int nt = 0; nt < 8; nt++)
                mma16816(acc[mt][nt], ah[mt], bh[nt]);
    }
}

template <int MODE, int BM, int BN, int NT>
__global__ __launch_bounds__(NT, 2)
void hmma_gemm_kernel(const float* __restrict__ bb, float* __restrict__ out) {
    constexpr int NCHUNK = (MODE == 1) ? 132 : 128;
    constexpr int MT = BM / 32;     // main: 4, h: 2
    extern __shared__ char smem[];
    uint32_t sbase = smem_u32(smem);

    int tid = threadIdx.x;
    int wid = tid >> 5, lane = tid & 31;
    int wm = wid & 1;
    int wn64 = wid >> 1;

    int m0, n0;
    if (MODE == 1) {
        int bid = blockIdx.x;
        int sg = bid >> 6, idx = bid & 63;      // 8x8 supergroups of 128x128 tiles
        int mg = sg & 7, ng = sg >> 3;
        m0 = (mg * 8 + (idx & 7)) * 128;
        n0 = (ng * 8 + (idx >> 3)) * 128;
    } else {
        m0 = blockIdx.x * BM; n0 = 0;
    }

    uint32_t aLane = (uint32_t)((lane & 15) * RS + (lane >> 4) * 16);
    uint32_t bLane = (uint32_t)(((lane & 7) + ((lane >> 4) & 1) * 8) * RS + ((lane >> 3) & 1) * 16);

    float acc[MT][8][4];
#pragma unroll
    for (int a = 0; a < MT; a++)
#pragma unroll
        for (int b = 0; b < 8; b++)
#pragma unroll
            for (int c = 0; c < 4; c++) acc[a][b][c] = 0.f;

    issue_chunk<MODE, BM, BN, NT>(sbase, 0, 0, m0, n0, tid); CP_COMMIT();
    issue_chunk<MODE, BM, BN, NT>(sbase, 1, 1, m0, n0, tid); CP_COMMIT();

#pragma unroll 1
    for (int i = 0; i < NCHUNK; i++) {
        CP_WAIT1();
        __syncthreads();
        if (i + 2 < NCHUNK) {
            int st = (i + 2) % NSTG;
            issue_chunk<MODE, BM, BN, NT>(sbase, st, i + 2, m0, n0, tid);
        }
        CP_COMMIT();
        compute_stage<BM, BN, MT>(sbase, i % NSTG, wm, wn64, aLane, bLane, acc);
    }

    // ---- epilogue ----
    int g = lane >> 2, t = lane & 3;
    if (MODE == 1) {
#pragma unroll
        for (int mt = 0; mt < MT; mt++) {
            int r0 = m0 + wm * (MT * 16) + mt * 16 + g;
#pragma unroll
            for (int nt = 0; nt < 8; nt++) {
                int cc = n0 + wn64 * 64 + nt * 8 + t * 2;
                float2 bv = *(const float2*)(bb + cc);
                float2 v0 = make_float2(acc[mt][nt][0] + bv.x, acc[mt][nt][1] + bv.y);
                float2 v1 = make_float2(acc[mt][nt][2] + bv.x, acc[mt][nt][3] + bv.y);
                *(float2*)(out + (size_t)r0 * ODIM + cc) = v0;
                *(float2*)(out + (size_t)(r0 + 8) * ODIM + cc) = v1;
            }
        }
    } else {
#pragma unroll
        for (int mt = 0; mt < MT; mt++) {
            int r0 = m0 + wm * (MT * 16) + mt * 16 + g;
            int r1 = r0 + 8;
#pragma unroll
            for (int nt = 0; nt < 8; nt++) {
                int cc = wn64 * 64 + nt * 8 + t * 2;
                int e = (wn64 * 64 + nt * 8) >> 4;
                float w0 = g_w[r0 * NEXP + e];
                float w1 = g_w[r1 * NEXP + e];
                *(__half2*)(g_gh + (size_t)r0 * KLORA + cc) =
                    __half2(__float2half_rn(acc[mt][nt][0] * w0), __float2half_rn(acc[mt][nt][1] * w0));
                *(__half2*)(g_gh + (size_t)r1 * KLORA + cc) =
                    __half2(__float2half_rn(acc[mt][nt][2] * w1), __float2half_rn(acc[mt][nt][3] * w1));
            }
        }
    }
}

// ---------------------------------------------------------------------------
extern "C" void kernel_launch(void* const* d_in, const int* in_sizes, int n_in,
                              void* d_out, int out_size) {
    const float* x  = (const float*)d_in[0];
    const float* Wb = (const float*)d_in[1];
    const float* bb = (const float*)d_in[2];
    const float* Wg = (const float*)d_in[3];
    const float* Wt = (const float*)d_in[4];
    const float* bt = (const float*)d_in[5];
    const float* Aw = (const float*)d_in[6];
    const float* Bw = (const float*)d_in[7];
    float* out = (float*)d_out;

    constexpr int SMEM_MAIN = NSTG * (128 * RS + 128 * RS);  // 61440 -> 2 CTAs/SM
    constexpr int SMEM_H    = NSTG * (64 * RS + 128 * RS);   // 46080 -> 2 CTAs/SM
    cudaFuncSetAttribute(hmma_gemm_kernel<1, 128, 128, 128>, cudaFuncAttributeMaxDynamicSharedMemorySize, SMEM_MAIN);
    cudaFuncSetAttribute(hmma_gemm_kernel<0, 64, 128, 128>, cudaFuncAttributeMaxDynamicSharedMemorySize, SMEM_H);

    prep_kernel<<<NB_TOTAL, 256>>>(x, Wb, Wg, Wt, bt, Aw, Bw);
    hmma_gemm_kernel<0, 64, 128, 128><<<NTOK / 64, 128, SMEM_H>>>(nullptr, nullptr);
    hmma_gemm_kernel<1, 128, 128, 128><<<(NTOK / 128) * (ODIM / 128), 128, SMEM_MAIN>>>(bb, out);
}

// round 12
// speedup vs baseline: 4.3400x; 1.0589x over previous
#include <cuda_runtime.h>
#include <cuda_fp16.h>
#include <cstdint>

#define NTOK 8192
#define DIM 4096
#define ODIM 4096
#define NEXP 8
#define RNK 16
#define KLORA 128
#define SCALING_F 2.0f
#define MAXTHR 0.125f

// ---------------- device scratch --------------------------------------------
__device__ float g_w[NTOK * NEXP];
__device__ __half g_xh[(size_t)NTOK * DIM];
__device__ __half g_Wh[(size_t)ODIM * DIM];
__device__ __half g_Ah[KLORA * DIM];
__device__ __half g_Bc[ODIM * KLORA];
__device__ __half g_gh[NTOK * KLORA];

// ---------------- PTX helpers -----------------------------------------------
__device__ __forceinline__ uint32_t smem_u32(const void* p) {
    uint32_t a;
    asm("{ .reg .u64 t; cvta.to.shared.u64 t, %1; cvt.u32.u64 %0, t; }" : "=r"(a) : "l"(p));
    return a;
}
__device__ __forceinline__ void cp16(uint32_t dst, const void* src) {
    asm volatile("cp.async.cg.shared.global [%0], [%1], 16;" :: "r"(dst), "l"(src));
}
#define CP_COMMIT() asm volatile("cp.async.commit_group;" ::: "memory")
#define CP_WAIT2()  asm volatile("cp.async.wait_group 2;" ::: "memory")

__device__ __forceinline__ void ldsm4(uint32_t& r0, uint32_t& r1, uint32_t& r2, uint32_t& r3,
                                      uint32_t addr) {
    asm volatile("ldmatrix.sync.aligned.m8n8.x4.shared.b16 {%0,%1,%2,%3}, [%4];"
                 : "=r"(r0), "=r"(r1), "=r"(r2), "=r"(r3) : "r"(addr));
}
__device__ __forceinline__ void mma16816(float* d, const uint32_t* a, const uint32_t* b) {
    asm volatile("mma.sync.aligned.m16n8k16.row.col.f32.f16.f16.f32 "
                 "{%0,%1,%2,%3}, {%4,%5,%6,%7}, {%8,%9}, {%0,%1,%2,%3};"
                 : "+f"(d[0]), "+f"(d[1]), "+f"(d[2]), "+f"(d[3])
                 : "r"(a[0]), "r"(a[1]), "r"(a[2]), "r"(a[3]), "r"(b[0]), "r"(b[1]));
}

// ---------------- fused prep kernel ------------------------------------------
#define NB_XG (NTOK / 4)                            // 2048
#define NB_WS (ODIM * DIM / 4 / 256)                // 16384
#define NB_AS (KLORA * DIM / 4 / 256)               // 512
#define NB_BC (ODIM * KLORA / 4 / 256)              // 512
#define NB_TOTAL (NB_XG + NB_WS + NB_AS + NB_BC)

__global__ __launch_bounds__(256)
void prep_kernel(const float* __restrict__ x,
                 const float* __restrict__ Wb,
                 const float* __restrict__ Wg,
                 const float* __restrict__ Wt,
                 const float* __restrict__ bt,
                 const float* __restrict__ Aw,
                 const float* __restrict__ Bw) {
    int bid = blockIdx.x;
    int tid = threadIdx.x;

    if (bid < NB_XG) {
        // ---- x convert + gate: 4 rows, 64 threads per row ----
        int n0 = bid * 4;
        int r = tid >> 6;
        int c = tid & 63;
        int row = n0 + r;
        const float4* xrow = (const float4*)x + (size_t)row * (DIM / 4);
        float acc[9];
#pragma unroll
        for (int i = 0; i < 9; i++) acc[i] = 0.f;

#pragma unroll 8
        for (int j = 0; j < 16; j++) {
            int idx = c + j * 64;
            float4 v = xrow[idx];
#pragma unroll
            for (int e = 0; e < NEXP; e++) {
                float4 wv = ((const float4*)Wg)[e * (DIM / 4) + idx];
                acc[e] = fmaf(v.x, wv.x, fmaf(v.y, wv.y, fmaf(v.z, wv.z, fmaf(v.w, wv.w, acc[e]))));
            }
            float4 wt = ((const float4*)Wt)[idx];
            acc[8] = fmaf(v.x, wt.x, fmaf(v.y, wt.y, fmaf(v.z, wt.z, fmaf(v.w, wt.w, acc[8]))));
            size_t o = (size_t)row * (DIM / 4) + idx;
            ((__half2*)g_xh)[2 * o]     = __half2(__float2half_rn(v.x), __float2half_rn(v.y));
            ((__half2*)g_xh)[2 * o + 1] = __half2(__float2half_rn(v.z), __float2half_rn(v.w));
        }
#pragma unroll
        for (int i = 0; i < 9; i++)
#pragma unroll
            for (int off = 16; off; off >>= 1)
                acc[i] += __shfl_down_sync(0xffffffffu, acc[i], off);
        __shared__ float sred[8][9];
        int warp = tid >> 5, lane = tid & 31;
        if (lane == 0)
#pragma unroll
            for (int i = 0; i < 9; i++) sred[warp][i] = acc[i];
        __syncthreads();
        if (tid < 4) {
            int t = tid;
            float v[9];
#pragma unroll
            for (int i = 0; i < 9; i++) v[i] = sred[2 * t][i] + sred[2 * t + 1][i];
            float mx = v[0];
#pragma unroll
            for (int e = 1; e < NEXP; e++) mx = fmaxf(mx, v[e]);
            float se = 0.f, gate[NEXP];
#pragma unroll
            for (int e = 0; e < NEXP; e++) { gate[e] = expf(v[e] - mx); se += gate[e]; }
            float inv = 1.f / se;
            float thr = MAXTHR / (1.f + expf(-(v[8] + bt[0])));
            float w[NEXP]; float ws = 0.f;
#pragma unroll
            for (int e = 0; e < NEXP; e++) {
                float a = gate[e] * inv - thr;
                w[e] = (a >= 0.f) ? a : 0.f;
                ws += w[e];
            }
            if (ws == 0.f) ws = 1.f;
            float sc = SCALING_F / ws;
#pragma unroll
            for (int e = 0; e < NEXP; e++) g_w[(n0 + t) * NEXP + e] = w[e] * sc;
        }
        return;
    }
    bid -= NB_XG;

    if (bid < NB_WS) {
        int i = bid * 256 + tid;
        float4 v = ((const float4*)Wb)[i];
        ((__half2*)g_Wh)[2 * i]     = __half2(__float2half_rn(v.x), __float2half_rn(v.y));
        ((__half2*)g_Wh)[2 * i + 1] = __half2(__float2half_rn(v.z), __float2half_rn(v.w));
        return;
    }
    bid -= NB_WS;

    if (bid < NB_AS) {
        int i = bid * 256 + tid;
        float4 v = ((const float4*)Aw)[i];
        ((__half2*)g_Ah)[2 * i]     = __half2(__float2half_rn(v.x), __float2half_rn(v.y));
        ((__half2*)g_Ah)[2 * i + 1] = __half2(__float2half_rn(v.z), __float2half_rn(v.w));
        return;
    }
    bid -= NB_AS;

    {
        int i = bid * 256 + tid;
        int idx = i * 4;
        int o = idx >> 7, k = idx & 127;
        int e = k >> 4, r = k & 15;
        const float* src = Bw + ((size_t)e * ODIM + o) * RNK + r;
        float4 v = *(const float4*)src;
        ((__half2*)g_Bc)[2 * i]     = __half2(__float2half_rn(v.x), __float2half_rn(v.y));
        ((__half2*)g_Bc)[2 * i + 1] = __half2(__float2half_rn(v.z), __float2half_rn(v.w));
        return;
    }
}

// ---------------- HMMA GEMM (single fp16 pass) --------------------------------
// smem rows of 32 fp16 (64B), row stride 80B => conflict-free ldmatrix
#define RS 80
#define NSTG 4

template <int MODE, int BM, int BN, int NT>
__device__ __forceinline__ void issue_chunk(uint32_t sbase, int stage, int chunk,
                                            int m0, int n0, int tid) {
    constexpr int AB = BM * RS;
    constexpr int BB = BN * RS;
    constexpr int STAGE_B = AB + BB;
    const __half *Ah, *Bh;
    int sA, sB, rA, rB, kcol;
    if (MODE == 1 && chunk >= 128) {
        kcol = (chunk - 128) * 32;
        Ah = g_gh; sA = KLORA; rA = m0;
        Bh = g_Bc; sB = KLORA; rB = n0;
    } else if (MODE == 1) {
        kcol = chunk * 32;
        Ah = g_xh; sA = DIM; rA = m0;
        Bh = g_Wh; sB = DIM; rB = n0;
    } else {
        kcol = chunk * 32;
        Ah = g_xh; sA = DIM; rA = m0;
        Bh = g_Ah; sB = DIM; rB = 0;
    }
    uint32_t base = sbase + stage * STAGE_B;
#pragma unroll
    for (int c = tid; c < BM * 4; c += NT) {
        int row = c >> 2, k16 = c & 3;
        uint32_t dof = row * RS + k16 * 16;
        cp16(base + dof, Ah + (size_t)(rA + row) * sA + kcol + k16 * 8);
    }
#pragma unroll
    for (int c = tid; c < BN * 4; c += NT) {
        int row = c >> 2, k16 = c & 3;
        uint32_t dof = row * RS + k16 * 16;
        cp16(base + AB + dof, Bh + (size_t)(rB + row) * sB + kcol + k16 * 8);
    }
}

template <int MT>
__device__ __forceinline__ void load_frags(uint32_t aB, uint32_t bB, int s,
                                           uint32_t ah[MT][4], uint32_t bh[8][2]) {
#pragma unroll
    for (int mt = 0; mt < MT; mt++)
        ldsm4(ah[mt][0], ah[mt][1], ah[mt][2], ah[mt][3], aB + mt * 16 * RS + s * 32);
#pragma unroll
    for (int p = 0; p < 4; p++)
        ldsm4(bh[2 * p][0], bh[2 * p][1], bh[2 * p + 1][0], bh[2 * p + 1][1],
              bB + p * 16 * RS + s * 32);
}

template <int BM, int BN, int MT>
__device__ __forceinline__ void compute_stage(uint32_t sbase, int stage, int wm, int wn64,
                                              uint32_t aLane, uint32_t bLane,
                                              float acc[MT][8][4]) {
    constexpr int AB = BM * RS;
    constexpr int BB = BN * RS;
    constexpr int STAGE_B = AB + BB;
    uint32_t base = sbase + stage * STAGE_B;
    uint32_t aB = base + wm * (MT * 16) * RS + aLane;
    uint32_t bB = base + AB + wn64 * 64 * RS + bLane;

    uint32_t ah[2][MT][4], bh[2][8][2];
    load_frags<MT>(aB, bB, 0, ah[0], bh[0]);
#pragma unroll
    for (int s = 0; s < 2; s++) {
        if (s == 0) load_frags<MT>(aB, bB, 1, ah[1], bh[1]);
#pragma unroll
        for (int mt = 0; mt < MT; mt++)
#pragma unroll
            for (int nt = 0; nt < 8; nt++)
                mma16816(acc[mt][nt], ah[s][mt], bh[s][nt]);
    }
}

template <int MODE, int BM, int BN, int NT>
__global__ __launch_bounds__(NT, 2)
void hmma_gemm_kernel(const float* __restrict__ bb, float* __restrict__ out) {
    constexpr int NCHUNK = (MODE == 1) ? 132 : 128;
    constexpr int MT = BM / 32;     // main: 4, h: 2
    extern __shared__ char smem[];
    uint32_t sbase = smem_u32(smem);

    int tid = threadIdx.x;
    int wid = tid >> 5, lane = tid & 31;
    int wm = wid & 1;
    int wn64 = wid >> 1;

    int m0, n0;
    if (MODE == 1) {
        int bid = blockIdx.x;
        int sg = bid >> 6, idx = bid & 63;      // 8x8 supergroups of 128x128 tiles
        int mg = sg & 7, ng = sg >> 3;
        m0 = (mg * 8 + (idx & 7)) * 128;
        n0 = (ng * 8 + (idx >> 3)) * 128;
    } else {
        m0 = blockIdx.x * BM; n0 = 0;
    }

    uint32_t aLane = (uint32_t)((lane & 15) * RS + (lane >> 4) * 16);
    uint32_t bLane = (uint32_t)(((lane & 7) + ((lane >> 4) & 1) * 8) * RS + ((lane >> 3) & 1) * 16);

    float acc[MT][8][4];
#pragma unroll
    for (int a = 0; a < MT; a++)
#pragma unroll
        for (int b = 0; b < 8; b++)
#pragma unroll
            for (int c = 0; c < 4; c++) acc[a][b][c] = 0.f;

    issue_chunk<MODE, BM, BN, NT>(sbase, 0, 0, m0, n0, tid); CP_COMMIT();
    issue_chunk<MODE, BM, BN, NT>(sbase, 1, 1, m0, n0, tid); CP_COMMIT();
    issue_chunk<MODE, BM, BN, NT>(sbase, 2, 2, m0, n0, tid); CP_COMMIT();

#pragma unroll 1
    for (int i = 0; i < NCHUNK; i++) {
        CP_WAIT2();
        __syncthreads();
        if (i + 3 < NCHUNK)
            issue_chunk<MODE, BM, BN, NT>(sbase, (i + 3) & (NSTG - 1), i + 3, m0, n0, tid);
        CP_COMMIT();
        compute_stage<BM, BN, MT>(sbase, i & (NSTG - 1), wm, wn64, aLane, bLane, acc);
    }

    // ---- epilogue ----
    int g = lane >> 2, t = lane & 3;
    if (MODE == 1) {
#pragma unroll
        for (int mt = 0; mt < MT; mt++) {
            int r0 = m0 + wm * (MT * 16) + mt * 16 + g;
#pragma unroll
            for (int nt = 0; nt < 8; nt++) {
                int cc = n0 + wn64 * 64 + nt * 8 + t * 2;
                float2 bv = *(const float2*)(bb + cc);
                float2 v0 = make_float2(acc[mt][nt][0] + bv.x, acc[mt][nt][1] + bv.y);
                float2 v1 = make_float2(acc[mt][nt][2] + bv.x, acc[mt][nt][3] + bv.y);
                *(float2*)(out + (size_t)r0 * ODIM + cc) = v0;
                *(float2*)(out + (size_t)(r0 + 8) * ODIM + cc) = v1;
            }
        }
    } else {
#pragma unroll
        for (int mt = 0; mt < MT; mt++) {
            int r0 = m0 + wm * (MT * 16) + mt * 16 + g;
            int r1 = r0 + 8;
#pragma unroll
            for (int nt = 0; nt < 8; nt++) {
                int cc = wn64 * 64 + nt * 8 + t * 2;
                int e = (wn64 * 64 + nt * 8) >> 4;
                float w0 = g_w[r0 * NEXP + e];
                float w1 = g_w[r1 * NEXP + e];
                *(__half2*)(g_gh + (size_t)r0 * KLORA + cc) =
                    __half2(__float2half_rn(acc[mt][nt][0] * w0), __float2half_rn(acc[mt][nt][1] * w0));
                *(__half2*)(g_gh + (size_t)r1 * KLORA + cc) =
                    __half2(__float2half_rn(acc[mt][nt][2] * w1), __float2half_rn(acc[mt][nt][3] * w1));
            }
        }
    }
}

// ---------------------------------------------------------------------------
extern "C" void kernel_launch(void* const* d_in, const int* in_sizes, int n_in,
                              void* d_out, int out_size) {
    const float* x  = (const float*)d_in[0];
    const float* Wb = (const float*)d_in[1];
    const float* bb = (const float*)d_in[2];
    const float* Wg = (const float*)d_in[3];
    const float* Wt = (const float*)d_in[4];
    const float* bt = (const float*)d_in[5];
    const float* Aw = (const float*)d_in[6];
    const float* Bw = (const float*)d_in[7];
    float* out = (float*)d_out;

    constexpr int SMEM_MAIN = NSTG * (128 * RS + 128 * RS);  // 81920 -> 2 CTAs/SM
    constexpr int SMEM_H    = NSTG * (64 * RS + 128 * RS);   // 61440 -> 2 CTAs/SM
    cudaFuncSetAttribute(hmma_gemm_kernel<1, 128, 128, 128>, cudaFuncAttributeMaxDynamicSharedMemorySize, SMEM_MAIN);
    cudaFuncSetAttribute(hmma_gemm_kernel<0, 64, 128, 128>, cudaFuncAttributeMaxDynamicSharedMemorySize, SMEM_H);

    prep_kernel<<<NB_TOTAL, 256>>>(x, Wb, Wg, Wt, bt, Aw, Bw);
    hmma_gemm_kernel<0, 64, 128, 128><<<NTOK / 64, 128, SMEM_H>>>(nullptr, nullptr);
    hmma_gemm_kernel<1, 128, 128, 128><<<(NTOK / 128) * (ODIM / 128), 128, SMEM_MAIN>>>(bb, out);
}